// round 1
// baseline (speedup 1.0000x reference)
#include <cuda_runtime.h>
#include <cuda_bf16.h>
#include <math.h>

// Problem dims (fixed for this problem)
#define BSZ    2
#define TLEN   2048
#define DM     1024
#define NST    16
#define DTRANK 64
#define SSMW   96          // dt_rank + 2*N
#define MTOT   (BSZ*TLEN)  // 4096

// scan chunking
#define NCHNK  64
#define CLEN   (TLEN/NCHNK)   // 32
// conv chunking
#define TCH    16
#define TLCH   (TLEN/TCH)     // 128

// ---------------- scratch (static __device__, no allocation) ----------------
__device__ float g_xr   [(size_t)MTOT * 2 * DM];   // in_proj output (x_in | res)
__device__ float g_xc   [(size_t)MTOT * DM];       // conv+silu output
__device__ float g_ssm  [(size_t)MTOT * SSMW];     // x_proj output
__device__ float g_delta[(size_t)MTOT * DM];       // softplus(dt)
__device__ float g_dxc  [(size_t)MTOT * DM];       // delta * xc
__device__ float g_y    [(size_t)MTOT * DM];       // gated scan output
__device__ float g_sp   [(size_t)BSZ * NCHNK * DM];            // per-chunk sum of delta
__device__ float g_hend [(size_t)BSZ * NCHNK * NST * DM];      // per-chunk local end state
__device__ float g_hinit[(size_t)BSZ * NCHNK * NST * DM];      // per-chunk initial state

// ---------------- generic fp32 NT GEMM: C = A(MxK) * B(NxK)^T + bias --------
// MODE 0: C = acc + bias
// MODE 1: C += acc + bias
// MODE 2: sp = softplus(acc+bias); C = sp; out2 = sp * xc   (delta / delta*xc)
template<int MODE>
__global__ void __launch_bounds__(256)
sgemm_nt(const float* __restrict__ A, int lda,
         const float* __restrict__ B, int ldb,
         const float* __restrict__ bias,
         float* __restrict__ C, int ldc,
         int M, int N, int K,
         const float* __restrict__ xc, float* __restrict__ out2)
{
    __shared__ float As[8][128];
    __shared__ float Bs[8][128];

    const int tid = threadIdx.x;
    const int bm  = blockIdx.y * 128;
    const int bn  = blockIdx.x * 128;
    const int tx  = tid & 15;        // 0..15
    const int ty  = tid >> 4;        // 0..15

    float acc[8][8];
#pragma unroll
    for (int i = 0; i < 8; i++)
#pragma unroll
        for (int j = 0; j < 8; j++) acc[i][j] = 0.f;

    const int lrow = tid >> 1;         // 0..127
    const int lk   = (tid & 1) * 4;    // 0 or 4
    const float* Aptr = A + (size_t)(bm + lrow) * lda + lk;
    const float* Bptr = B + (size_t)(bn + lrow) * ldb + lk;
    const bool bvalid = (bn + lrow) < N;

    for (int k0 = 0; k0 < K; k0 += 8) {
        float4 av = *(const float4*)(Aptr + k0);
        float4 bv = bvalid ? *(const float4*)(Bptr + k0) : make_float4(0.f, 0.f, 0.f, 0.f);
        __syncthreads();
        As[lk + 0][lrow] = av.x; As[lk + 1][lrow] = av.y;
        As[lk + 2][lrow] = av.z; As[lk + 3][lrow] = av.w;
        Bs[lk + 0][lrow] = bv.x; Bs[lk + 1][lrow] = bv.y;
        Bs[lk + 2][lrow] = bv.z; Bs[lk + 3][lrow] = bv.w;
        __syncthreads();
#pragma unroll
        for (int kk = 0; kk < 8; kk++) {
            float4 a0 = *(const float4*)&As[kk][ty * 8];
            float4 a1 = *(const float4*)&As[kk][ty * 8 + 4];
            float4 b0 = *(const float4*)&Bs[kk][tx * 8];
            float4 b1 = *(const float4*)&Bs[kk][tx * 8 + 4];
            float a[8] = {a0.x, a0.y, a0.z, a0.w, a1.x, a1.y, a1.z, a1.w};
            float b[8] = {b0.x, b0.y, b0.z, b0.w, b1.x, b1.y, b1.z, b1.w};
#pragma unroll
            for (int i = 0; i < 8; i++)
#pragma unroll
                for (int j = 0; j < 8; j++)
                    acc[i][j] = fmaf(a[i], b[j], acc[i][j]);
        }
    }

#pragma unroll
    for (int i = 0; i < 8; i++) {
        int row = bm + ty * 8 + i;
#pragma unroll
        for (int j = 0; j < 8; j++) {
            int col = bn + tx * 8 + j;
            if (col < N) {
                float v = acc[i][j] + bias[col];
                size_t idx = (size_t)row * ldc + col;
                if (MODE == 0) {
                    C[idx] = v;
                } else if (MODE == 1) {
                    C[idx] += v;
                } else {
                    float sp = (v > 20.f) ? v : log1pf(expf(v));
                    C[idx] = sp;
                    out2[idx] = sp * xc[idx];
                }
            }
        }
    }
}

// ---------------- depthwise causal conv (k=4) + silu ------------------------
__global__ void conv_silu(const float* __restrict__ cw, const float* __restrict__ cb)
{
    int gid = blockIdx.x * blockDim.x + threadIdx.x;
    if (gid >= BSZ * DM * TCH) return;
    int d  = gid % DM;
    int r  = gid / DM;
    int tc = r % TCH;
    int b  = r / TCH;

    float w0 = cw[d * 4 + 0], w1 = cw[d * 4 + 1], w2 = cw[d * 4 + 2], w3 = cw[d * 4 + 3];
    float bias = cb[d];
    int t0 = tc * TLCH;

    const float* xin = g_xr + (size_t)b * TLEN * 2 * DM + d;  // stride 2*DM per t
    float xm3 = (t0 - 3 >= 0) ? xin[(size_t)(t0 - 3) * 2 * DM] : 0.f;
    float xm2 = (t0 - 2 >= 0) ? xin[(size_t)(t0 - 2) * 2 * DM] : 0.f;
    float xm1 = (t0 - 1 >= 0) ? xin[(size_t)(t0 - 1) * 2 * DM] : 0.f;

    for (int i = 0; i < TLCH; i++) {
        int t = t0 + i;
        float x0 = xin[(size_t)t * 2 * DM];
        float a = bias;
        a = fmaf(w0, xm3, a);
        a = fmaf(w1, xm2, a);
        a = fmaf(w2, xm1, a);
        a = fmaf(w3, x0, a);
        float s = a / (1.f + __expf(-a));
        g_xc[(size_t)(b * TLEN + t) * DM + d] = s;
        xm3 = xm2; xm2 = xm1; xm1 = x0;
    }
}

// ---------------- scan pass A: per-chunk local scan (h0 = 0) ----------------
__global__ void scan_passA(const float* __restrict__ A_log)
{
    int gid = blockIdx.x * blockDim.x + threadIdx.x;
    if (gid >= BSZ * NCHNK * DM) return;
    int d = gid % DM;
    int r = gid / DM;
    int c = r % NCHNK;
    int b = r / NCHNK;

    float Ac[NST];
#pragma unroll
    for (int n = 0; n < NST; n++) Ac[n] = -__expf(A_log[n]);

    float h[NST];
#pragma unroll
    for (int n = 0; n < NST; n++) h[n] = 0.f;
    float sp = 0.f;

    int m0 = b * TLEN + c * CLEN;
    for (int i = 0; i < CLEN; i++) {
        int m = m0 + i;
        float de = g_delta[(size_t)m * DM + d];
        float dx = g_dxc[(size_t)m * DM + d];
        sp += de;
        const float4* bp = (const float4*)(g_ssm + (size_t)m * SSMW + DTRANK);
#pragma unroll
        for (int q = 0; q < 4; q++) {
            float4 bv = bp[q];
            h[4*q+0] = fmaf(__expf(Ac[4*q+0] * de), h[4*q+0], dx * bv.x);
            h[4*q+1] = fmaf(__expf(Ac[4*q+1] * de), h[4*q+1], dx * bv.y);
            h[4*q+2] = fmaf(__expf(Ac[4*q+2] * de), h[4*q+2], dx * bv.z);
            h[4*q+3] = fmaf(__expf(Ac[4*q+3] * de), h[4*q+3], dx * bv.w);
        }
    }

    g_sp[(size_t)(b * NCHNK + c) * DM + d] = sp;
    size_t base = (size_t)((b * NCHNK + c) * NST) * DM + d;
#pragma unroll
    for (int n = 0; n < NST; n++) g_hend[base + (size_t)n * DM] = h[n];
}

// ---------------- scan combine: sequential over chunks ----------------------
__global__ void scan_combine(const float* __restrict__ A_log)
{
    int gid = blockIdx.x * blockDim.x + threadIdx.x;
    if (gid >= BSZ * DM) return;
    int d = gid % DM;
    int b = gid / DM;

    float Ac[NST];
#pragma unroll
    for (int n = 0; n < NST; n++) Ac[n] = -__expf(A_log[n]);

    float h[NST];
#pragma unroll
    for (int n = 0; n < NST; n++) h[n] = 0.f;

    for (int c = 0; c < NCHNK; c++) {
        size_t base = (size_t)((b * NCHNK + c) * NST) * DM + d;
        float sp = g_sp[(size_t)(b * NCHNK + c) * DM + d];
#pragma unroll
        for (int n = 0; n < NST; n++) {
            g_hinit[base + (size_t)n * DM] = h[n];
            h[n] = fmaf(__expf(Ac[n] * sp), h[n], g_hend[base + (size_t)n * DM]);
        }
    }
}

// ---------------- scan pass B: replay with true init, emit gated y ----------
__global__ void scan_passB(const float* __restrict__ A_log, const float* __restrict__ D_param)
{
    int gid = blockIdx.x * blockDim.x + threadIdx.x;
    if (gid >= BSZ * NCHNK * DM) return;
    int d = gid % DM;
    int r = gid / DM;
    int c = r % NCHNK;
    int b = r / NCHNK;

    float Ac[NST];
#pragma unroll
    for (int n = 0; n < NST; n++) Ac[n] = -__expf(A_log[n]);

    float h[NST];
    size_t base = (size_t)((b * NCHNK + c) * NST) * DM + d;
#pragma unroll
    for (int n = 0; n < NST; n++) h[n] = g_hinit[base + (size_t)n * DM];

    float Dp = D_param[d];
    int m0 = b * TLEN + c * CLEN;

    for (int i = 0; i < CLEN; i++) {
        int m = m0 + i;
        float de = g_delta[(size_t)m * DM + d];
        float dx = g_dxc[(size_t)m * DM + d];
        const float4* bp = (const float4*)(g_ssm + (size_t)m * SSMW + DTRANK);
        const float4* cp = (const float4*)(g_ssm + (size_t)m * SSMW + DTRANK + NST);
        float y = 0.f;
#pragma unroll
        for (int q = 0; q < 4; q++) {
            float4 bv = bp[q];
            float4 cv = cp[q];
            h[4*q+0] = fmaf(__expf(Ac[4*q+0] * de), h[4*q+0], dx * bv.x);
            y = fmaf(h[4*q+0], cv.x, y);
            h[4*q+1] = fmaf(__expf(Ac[4*q+1] * de), h[4*q+1], dx * bv.y);
            y = fmaf(h[4*q+1], cv.y, y);
            h[4*q+2] = fmaf(__expf(Ac[4*q+2] * de), h[4*q+2], dx * bv.z);
            y = fmaf(h[4*q+2], cv.z, y);
            h[4*q+3] = fmaf(__expf(Ac[4*q+3] * de), h[4*q+3], dx * bv.w);
            y = fmaf(h[4*q+3], cv.w, y);
        }
        float xcv = g_xc[(size_t)m * DM + d];
        y = fmaf(xcv, Dp, y);
        float res = g_xr[(size_t)m * 2 * DM + DM + d];
        float gate = res / (1.f + __expf(-res));
        g_y[(size_t)m * DM + d] = y * gate;
    }
}

// ---------------- host launcher ---------------------------------------------
extern "C" void kernel_launch(void* const* d_in, const int* in_sizes, int n_in,
                              void* d_out, int out_size)
{
    const float* x        = (const float*)d_in[0];
    const float* in_w     = (const float*)d_in[1];
    const float* in_b     = (const float*)d_in[2];
    const float* conv_w   = (const float*)d_in[3];
    const float* conv_b   = (const float*)d_in[4];
    const float* xproj_w  = (const float*)d_in[5];
    const float* xproj_b  = (const float*)d_in[6];
    const float* dt_w     = (const float*)d_in[7];
    const float* dt_b     = (const float*)d_in[8];
    const float* A_log    = (const float*)d_in[9];
    const float* D_param  = (const float*)d_in[10];
    const float* out_w    = (const float*)d_in[11];
    const float* out_b    = (const float*)d_in[12];
    const float* skip_w   = (const float*)d_in[13];
    const float* skip_b   = (const float*)d_in[14];
    float* out = (float*)d_out;

    float *p_xr, *p_xc, *p_ssm, *p_delta, *p_dxc, *p_y;
    cudaGetSymbolAddress((void**)&p_xr,    g_xr);
    cudaGetSymbolAddress((void**)&p_xc,    g_xc);
    cudaGetSymbolAddress((void**)&p_ssm,   g_ssm);
    cudaGetSymbolAddress((void**)&p_delta, g_delta);
    cudaGetSymbolAddress((void**)&p_dxc,   g_dxc);
    cudaGetSymbolAddress((void**)&p_y,     g_y);

    // 1) xr = x @ in_proj_w^T + b   (4096 x 2048, K=1024)
    {
        dim3 g(2 * DM / 128, MTOT / 128);
        sgemm_nt<0><<<g, 256>>>(x, DM, in_w, DM, in_b, p_xr, 2 * DM,
                                MTOT, 2 * DM, DM, nullptr, nullptr);
    }
    // 2) depthwise conv + silu -> g_xc
    conv_silu<<<(BSZ * DM * TCH) / 256, 256>>>(conv_w, conv_b);
    // 3) ssm = xc @ x_proj_w^T + b  (4096 x 96, K=1024)
    {
        dim3 g(1, MTOT / 128);
        sgemm_nt<0><<<g, 256>>>(p_xc, DM, xproj_w, DM, xproj_b, p_ssm, SSMW,
                                MTOT, SSMW, DM, nullptr, nullptr);
    }
    // 4) delta = softplus(ssm[:, :64] @ dt_proj_w^T + b); dxc = delta*xc
    {
        dim3 g(DM / 128, MTOT / 128);
        sgemm_nt<2><<<g, 256>>>(p_ssm, SSMW, dt_w, DTRANK, dt_b, p_delta, DM,
                                MTOT, DM, DTRANK, p_xc, p_dxc);
    }
    // 5) chunked selective scan
    scan_passA<<<(BSZ * NCHNK * DM) / 256, 256>>>(A_log);
    scan_combine<<<(BSZ * DM) / 256, 256>>>(A_log);
    scan_passB<<<(BSZ * NCHNK * DM) / 256, 256>>>(A_log, D_param);
    // 6) out = y @ out_proj_w^T + out_b ; out += x @ skip_proj_w^T + skip_b
    {
        dim3 g(DM / 128, MTOT / 128);
        sgemm_nt<0><<<g, 256>>>(p_y, DM, out_w, DM, out_b, out, DM,
                                MTOT, DM, DM, nullptr, nullptr);
        sgemm_nt<1><<<g, 256>>>(x, DM, skip_w, DM, skip_b, out, DM,
                                MTOT, DM, DM, nullptr, nullptr);
    }
}

// round 3
// speedup vs baseline: 2.5531x; 2.5531x over previous
#include <cuda_runtime.h>
#include <cuda_bf16.h>
#include <math.h>
#include <stdint.h>

// ---------------- problem dims ----------------
#define BSZ    2
#define TLEN   2048
#define DM     1024
#define NST    16
#define DTRANK 64
#define SSMW   96
#define MTOT   (BSZ*TLEN)     // 4096
#define NCHNK  64
#define CLEN   (TLEN/NCHNK)   // 32
#define TCH    16
#define TLCH   (TLEN/TCH)     // 128

// ---------------- device scratch (no allocations) ----------------
__device__ float g_xr   [(size_t)MTOT * 2 * DM];
__device__ float g_xc   [(size_t)MTOT * DM];
__device__ __nv_bfloat16 g_xchi[(size_t)MTOT * DM];
__device__ __nv_bfloat16 g_xclo[(size_t)MTOT * DM];
__device__ float g_ssm  [(size_t)MTOT * SSMW];
__device__ __nv_bfloat16 g_dthi[(size_t)MTOT * DTRANK];
__device__ __nv_bfloat16 g_dtlo[(size_t)MTOT * DTRANK];
__device__ float g_delta[(size_t)MTOT * DM];
__device__ float g_dxc  [(size_t)MTOT * DM];
__device__ float g_sp   [(size_t)BSZ * NCHNK * DM];
__device__ float g_hend [(size_t)BSZ * NCHNK * NST * DM];
__device__ float g_hinit[(size_t)BSZ * NCHNK * NST * DM];
// A2 = [y | x] (4096 x 2048) bf16 hi/lo ; x part doubles as in_proj A
__device__ __nv_bfloat16 g_A2hi[(size_t)MTOT * 2 * DM];
__device__ __nv_bfloat16 g_A2lo[(size_t)MTOT * 2 * DM];
// weight splits
__device__ __nv_bfloat16 g_Binhi[(size_t)2 * DM * DM];
__device__ __nv_bfloat16 g_Binlo[(size_t)2 * DM * DM];
__device__ __nv_bfloat16 g_Bxphi[(size_t)SSMW * DM];
__device__ __nv_bfloat16 g_Bxplo[(size_t)SSMW * DM];
__device__ __nv_bfloat16 g_Bdthi[(size_t)DM * DTRANK];
__device__ __nv_bfloat16 g_Bdtlo[(size_t)DM * DTRANK];
__device__ __nv_bfloat16 g_B2hi[(size_t)DM * 2 * DM];   // [Wout | Wskip]
__device__ __nv_bfloat16 g_B2lo[(size_t)DM * 2 * DM];

// ---------------- helpers ----------------
__device__ __forceinline__ uint32_t smem_u32(const void* p) {
    uint32_t a;
    asm("{ .reg .u64 t; cvta.to.shared.u64 t, %1; cvt.u32.u64 %0, t; }" : "=r"(a) : "l"(p));
    return a;
}
#define SW128(o) ((o) ^ (((o) >> 3) & 0x70))

__device__ __forceinline__ void ldm_x4(uint32_t* r, uint32_t addr) {
    asm volatile("ldmatrix.sync.aligned.m8n8.x4.shared.b16 {%0,%1,%2,%3}, [%4];"
                 : "=r"(r[0]), "=r"(r[1]), "=r"(r[2]), "=r"(r[3]) : "r"(addr));
}
__device__ __forceinline__ void mma_bf16(float* d, const uint32_t* a, const uint32_t* b) {
    asm volatile("mma.sync.aligned.m16n8k16.row.col.f32.bf16.bf16.f32 "
                 "{%0,%1,%2,%3}, {%4,%5,%6,%7}, {%8,%9}, {%0,%1,%2,%3};"
                 : "+f"(d[0]), "+f"(d[1]), "+f"(d[2]), "+f"(d[3])
                 : "r"(a[0]), "r"(a[1]), "r"(a[2]), "r"(a[3]), "r"(b[0]), "r"(b[1]));
}

#define STG_STRIDE 65536
#define GSMEM (2 * STG_STRIDE)    // 131072

// ---------------- HMMA bf16-split GEMM: C(128x128 tile) = A*B^T -------------
// A: [M x K] bf16 hi/lo (row-major, lda). B: [N x K] bf16 hi/lo (row-major, ldb).
// Per K-stage of 64: smem tiles Ahi|Alo|Bhi|Blo, 128x64 bf16 each, SW128 rows.
// MODE 0: C = acc + bias (+ bias2)
// MODE 1: ssm fp32 (ldc=96) + dt bf16 hi/lo
// MODE 2: delta = softplus(acc+bias); dxc = delta*xc
template<int MODE>
__global__ void __launch_bounds__(256, 1)
gemm_mma(const __nv_bfloat16* __restrict__ Ahi, const __nv_bfloat16* __restrict__ Alo, int lda,
         const __nv_bfloat16* __restrict__ Bhi, const __nv_bfloat16* __restrict__ Blo, int ldb,
         int Ntot, int KT,
         const float* __restrict__ bias, const float* __restrict__ bias2,
         float* __restrict__ C, int ldc,
         const float* __restrict__ fxc, float* __restrict__ aux,
         __nv_bfloat16* __restrict__ dthi, __nv_bfloat16* __restrict__ dtlo)
{
    extern __shared__ char smem[];
    const uint32_t sb  = smem_u32(smem);
    const int tid  = threadIdx.x;
    const int wid  = tid >> 5;
    const int lane = tid & 31;
    const int bm   = blockIdx.y * 128;
    const int bn   = blockIdx.x * 128;
    const int wrow = (wid & 3) * 32;   // warp M offset
    const int wcol = (wid >> 2) * 64;  // warp N offset

    float acc[2][8][4];
#pragma unroll
    for (int m = 0; m < 2; m++)
#pragma unroll
        for (int n = 0; n < 8; n++)
#pragma unroll
            for (int v = 0; v < 4; v++) acc[m][n][v] = 0.f;

    auto load_stage = [&](int kt, int s) {
        uint32_t stg = sb + s * STG_STRIDE;
        int koff = kt * 64;
#pragma unroll
        for (int sub = 0; sub < 4; sub++) {
            const __nv_bfloat16* base = (sub == 0) ? Ahi : (sub == 1) ? Alo : (sub == 2) ? Bhi : Blo;
            const int ld = (sub < 2) ? lda : ldb;
            const bool isB = (sub >= 2);
#pragma unroll
            for (int i = 0; i < 4; i++) {
                int chunk = tid + i * 256;           // 0..1023: 128 rows x 8 16B-chunks
                int row = chunk >> 3, c16 = chunk & 7;
                uint32_t dst = stg + sub * 16384 + SW128(row * 128 + c16 * 16);
                int gr = (isB ? bn : bm) + row;
                int sz = 16;
                if (isB && gr >= Ntot) { gr = 0; sz = 0; }
                const __nv_bfloat16* src = base + (size_t)gr * ld + koff + c16 * 8;
                asm volatile("cp.async.cg.shared.global [%0], [%1], 16, %2;"
                             :: "r"(dst), "l"(src), "r"(sz) : "memory");
            }
        }
        asm volatile("cp.async.commit_group;" ::: "memory");
    };

    const int g = lane >> 3, r = lane & 7;

    load_stage(0, 0);
    for (int kt = 0; kt < KT; kt++) {
        if (kt + 1 < KT) {
            load_stage(kt + 1, (kt + 1) & 1);
            asm volatile("cp.async.wait_group 1;" ::: "memory");
        } else {
            asm volatile("cp.async.wait_group 0;" ::: "memory");
        }
        __syncthreads();

        uint32_t stg = sb + (kt & 1) * STG_STRIDE;
#pragma unroll
        for (int ks = 0; ks < 4; ks++) {
            const int kByte = ks * 32;   // 16 bf16 = 32B
            // A fragments: tiles [m0k0, m8k0, m0k8, m8k8]
            uint32_t ahi[2][4], alo[2][4];
#pragma unroll
            for (int m = 0; m < 2; m++) {
                uint32_t off = SW128((wrow + m * 16 + (g & 1) * 8 + r) * 128 + kByte + (g >> 1) * 16);
                ldm_x4(ahi[m], stg + off);
                ldm_x4(alo[m], stg + 16384 + off);
            }
            // B fragments: tiles [n0k0, n0k8, n8k0, n8k8] per n16 block
            uint32_t bhi[8][2], blo[8][2];
#pragma unroll
            for (int nb = 0; nb < 4; nb++) {
                uint32_t off = SW128((wcol + nb * 16 + (g >> 1) * 8 + r) * 128 + kByte + (g & 1) * 16);
                uint32_t t[4];
                ldm_x4(t, stg + 32768 + off);
                bhi[nb * 2][0] = t[0]; bhi[nb * 2][1] = t[1];
                bhi[nb * 2 + 1][0] = t[2]; bhi[nb * 2 + 1][1] = t[3];
                ldm_x4(t, stg + 49152 + off);
                blo[nb * 2][0] = t[0]; blo[nb * 2][1] = t[1];
                blo[nb * 2 + 1][0] = t[2]; blo[nb * 2 + 1][1] = t[3];
            }
#pragma unroll
            for (int m = 0; m < 2; m++)
#pragma unroll
                for (int n = 0; n < 8; n++) {
                    mma_bf16(acc[m][n], ahi[m], bhi[n]);
                    mma_bf16(acc[m][n], ahi[m], blo[n]);
                    mma_bf16(acc[m][n], alo[m], bhi[n]);
                }
        }
        __syncthreads();
    }

    // stage accumulators through smem for coalesced epilogue
    float* epi = (float*)smem;
#pragma unroll
    for (int m = 0; m < 2; m++)
#pragma unroll
        for (int n = 0; n < 8; n++) {
            int row = wrow + m * 16 + (lane >> 2);
            int col = wcol + n * 8 + (lane & 3) * 2;
            epi[row * 128 + col]           = acc[m][n][0];
            epi[row * 128 + col + 1]       = acc[m][n][1];
            epi[(row + 8) * 128 + col]     = acc[m][n][2];
            epi[(row + 8) * 128 + col + 1] = acc[m][n][3];
        }
    __syncthreads();

    const float4* epi4 = (const float4*)epi;
    if (MODE == 0) {
#pragma unroll 4
        for (int i = 0; i < 16; i++) {
            int e = tid + i * 256;
            int row = e >> 5, c4 = e & 31;
            float4 v = epi4[e];
            int n = bn + c4 * 4;
            v.x += bias[n + 0]; v.y += bias[n + 1]; v.z += bias[n + 2]; v.w += bias[n + 3];
            if (bias2) {
                v.x += bias2[n + 0]; v.y += bias2[n + 1]; v.z += bias2[n + 2]; v.w += bias2[n + 3];
            }
            *(float4*)(C + (size_t)(bm + row) * ldc + n) = v;
        }
    } else if (MODE == 2) {
#pragma unroll 4
        for (int i = 0; i < 16; i++) {
            int e = tid + i * 256;
            int row = e >> 5, c4 = e & 31;
            float4 v = epi4[e];
            int n = bn + c4 * 4;
            v.x += bias[n + 0]; v.y += bias[n + 1]; v.z += bias[n + 2]; v.w += bias[n + 3];
            size_t idx = (size_t)(bm + row) * DM + n;
            float4 xcv = *(const float4*)(fxc + idx);
            float4 sp;
            sp.x = (v.x > 20.f) ? v.x : log1pf(expf(v.x));
            sp.y = (v.y > 20.f) ? v.y : log1pf(expf(v.y));
            sp.z = (v.z > 20.f) ? v.z : log1pf(expf(v.z));
            sp.w = (v.w > 20.f) ? v.w : log1pf(expf(v.w));
            *(float4*)(C + idx) = sp;
            float4 dx = make_float4(sp.x * xcv.x, sp.y * xcv.y, sp.z * xcv.z, sp.w * xcv.w);
            *(float4*)(aux + idx) = dx;
        }
    } else { // MODE 1: x_proj, Ntot = 96
        for (int i = 0; i < 16; i++) {
            int e = tid + i * 256;
            int row = e >> 5, c4 = e & 31;
            if (c4 >= 24) continue;
            float4 v = epi4[e];
            int n = c4 * 4;
            v.x += bias[n + 0]; v.y += bias[n + 1]; v.z += bias[n + 2]; v.w += bias[n + 3];
            *(float4*)(C + (size_t)(bm + row) * SSMW + n) = v;
            if (c4 < 16) {
                size_t di = (size_t)(bm + row) * DTRANK + n;
                float vv[4] = {v.x, v.y, v.z, v.w};
#pragma unroll
                for (int j = 0; j < 4; j++) {
                    __nv_bfloat16 h = __float2bfloat16(vv[j]);
                    dthi[di + j] = h;
                    dtlo[di + j] = __float2bfloat16(vv[j] - __bfloat162float(h));
                }
            }
        }
    }
}

// ---------------- elementwise converts ----------------
__global__ void split_pair(const float* __restrict__ s, __nv_bfloat16* __restrict__ hi,
                           __nv_bfloat16* __restrict__ lo, int n)
{
    int i = blockIdx.x * 256 + threadIdx.x;
    if (i < n) {
        float v = s[i];
        __nv_bfloat16 h = __float2bfloat16(v);
        hi[i] = h;
        lo[i] = __float2bfloat16(v - __bfloat162float(h));
    }
}
__global__ void split_x_A2(const float* __restrict__ x)
{
    int i = blockIdx.x * 256 + threadIdx.x;
    int m = i >> 10, c = i & 1023;
    float v = x[i];
    __nv_bfloat16 h = __float2bfloat16(v);
    size_t o = (size_t)m * 2048 + 1024 + c;
    g_A2hi[o] = h;
    g_A2lo[o] = __float2bfloat16(v - __bfloat162float(h));
}
__global__ void pack_ws(const float* __restrict__ wo, const float* __restrict__ ws)
{
    int i = blockIdx.x * 256 + threadIdx.x;
    int m = i >> 10, c = i & 1023;
    size_t o = (size_t)m * 2048;
    float v = wo[i];
    __nv_bfloat16 h = __float2bfloat16(v);
    g_B2hi[o + c] = h;
    g_B2lo[o + c] = __float2bfloat16(v - __bfloat162float(h));
    v = ws[i];
    h = __float2bfloat16(v);
    g_B2hi[o + 1024 + c] = h;
    g_B2lo[o + 1024 + c] = __float2bfloat16(v - __bfloat162float(h));
}

// ---------------- depthwise causal conv (k=4) + silu + bf16 split -----------
__global__ void conv_silu(const float* __restrict__ cw, const float* __restrict__ cb)
{
    int gid = blockIdx.x * blockDim.x + threadIdx.x;
    if (gid >= BSZ * DM * TCH) return;
    int d  = gid % DM;
    int r  = gid / DM;
    int tc = r % TCH;
    int b  = r / TCH;

    float w0 = cw[d * 4 + 0], w1 = cw[d * 4 + 1], w2 = cw[d * 4 + 2], w3 = cw[d * 4 + 3];
    float bias = cb[d];
    int t0 = tc * TLCH;

    const float* xin = g_xr + (size_t)b * TLEN * 2 * DM + d;
    float xm3 = (t0 - 3 >= 0) ? xin[(size_t)(t0 - 3) * 2 * DM] : 0.f;
    float xm2 = (t0 - 2 >= 0) ? xin[(size_t)(t0 - 2) * 2 * DM] : 0.f;
    float xm1 = (t0 - 1 >= 0) ? xin[(size_t)(t0 - 1) * 2 * DM] : 0.f;

    for (int i = 0; i < TLCH; i++) {
        int t = t0 + i;
        float x0 = xin[(size_t)t * 2 * DM];
        float a = bias;
        a = fmaf(w0, xm3, a); a = fmaf(w1, xm2, a);
        a = fmaf(w2, xm1, a); a = fmaf(w3, x0, a);
        float s = a / (1.f + __expf(-a));
        size_t o = (size_t)(b * TLEN + t) * DM + d;
        g_xc[o] = s;
        __nv_bfloat16 h = __float2bfloat16(s);
        g_xchi[o] = h;
        g_xclo[o] = __float2bfloat16(s - __bfloat162float(h));
        xm3 = xm2; xm2 = xm1; xm1 = x0;
    }
}

// ---------------- chunked selective scan ----------------
__global__ void scan_passA(const float* __restrict__ A_log)
{
    int gid = blockIdx.x * blockDim.x + threadIdx.x;
    if (gid >= BSZ * NCHNK * DM) return;
    int d = gid % DM;
    int r = gid / DM;
    int c = r % NCHNK;
    int b = r / NCHNK;

    float Ac[NST];
#pragma unroll
    for (int n = 0; n < NST; n++) Ac[n] = -__expf(A_log[n]);
    float h[NST];
#pragma unroll
    for (int n = 0; n < NST; n++) h[n] = 0.f;
    float sp = 0.f;

    int m0 = b * TLEN + c * CLEN;
    for (int i = 0; i < CLEN; i++) {
        int m = m0 + i;
        float de = g_delta[(size_t)m * DM + d];
        float dx = g_dxc[(size_t)m * DM + d];
        sp += de;
        const float4* bp = (const float4*)(g_ssm + (size_t)m * SSMW + DTRANK);
#pragma unroll
        for (int q = 0; q < 4; q++) {
            float4 bv = bp[q];
            h[4*q+0] = fmaf(__expf(Ac[4*q+0] * de), h[4*q+0], dx * bv.x);
            h[4*q+1] = fmaf(__expf(Ac[4*q+1] * de), h[4*q+1], dx * bv.y);
            h[4*q+2] = fmaf(__expf(Ac[4*q+2] * de), h[4*q+2], dx * bv.z);
            h[4*q+3] = fmaf(__expf(Ac[4*q+3] * de), h[4*q+3], dx * bv.w);
        }
    }
    g_sp[(size_t)(b * NCHNK + c) * DM + d] = sp;
    size_t base = (size_t)((b * NCHNK + c) * NST) * DM + d;
#pragma unroll
    for (int n = 0; n < NST; n++) g_hend[base + (size_t)n * DM] = h[n];
}

__global__ void scan_combine(const float* __restrict__ A_log)
{
    int gid = blockIdx.x * blockDim.x + threadIdx.x;
    if (gid >= BSZ * DM) return;
    int d = gid % DM;
    int b = gid / DM;

    float Ac[NST];
#pragma unroll
    for (int n = 0; n < NST; n++) Ac[n] = -__expf(A_log[n]);
    float h[NST];
#pragma unroll
    for (int n = 0; n < NST; n++) h[n] = 0.f;

    for (int c = 0; c < NCHNK; c++) {
        size_t base = (size_t)((b * NCHNK + c) * NST) * DM + d;
        float sp = g_sp[(size_t)(b * NCHNK + c) * DM + d];
#pragma unroll
        for (int n = 0; n < NST; n++) {
            g_hinit[base + (size_t)n * DM] = h[n];
            h[n] = fmaf(__expf(Ac[n] * sp), h[n], g_hend[base + (size_t)n * DM]);
        }
    }
}

__global__ void scan_passB(const float* __restrict__ A_log, const float* __restrict__ D_param)
{
    int gid = blockIdx.x * blockDim.x + threadIdx.x;
    if (gid >= BSZ * NCHNK * DM) return;
    int d = gid % DM;
    int r = gid / DM;
    int c = r % NCHNK;
    int b = r / NCHNK;

    float Ac[NST];
#pragma unroll
    for (int n = 0; n < NST; n++) Ac[n] = -__expf(A_log[n]);
    float h[NST];
    size_t base = (size_t)((b * NCHNK + c) * NST) * DM + d;
#pragma unroll
    for (int n = 0; n < NST; n++) h[n] = g_hinit[base + (size_t)n * DM];

    float Dp = D_param[d];
    int m0 = b * TLEN + c * CLEN;

    for (int i = 0; i < CLEN; i++) {
        int m = m0 + i;
        float de = g_delta[(size_t)m * DM + d];
        float dx = g_dxc[(size_t)m * DM + d];
        const float4* bp = (const float4*)(g_ssm + (size_t)m * SSMW + DTRANK);
        const float4* cp = (const float4*)(g_ssm + (size_t)m * SSMW + DTRANK + NST);
        float y = 0.f;
#pragma unroll
        for (int q = 0; q < 4; q++) {
            float4 bv = bp[q];
            float4 cv = cp[q];
            h[4*q+0] = fmaf(__expf(Ac[4*q+0] * de), h[4*q+0], dx * bv.x); y = fmaf(h[4*q+0], cv.x, y);
            h[4*q+1] = fmaf(__expf(Ac[4*q+1] * de), h[4*q+1], dx * bv.y); y = fmaf(h[4*q+1], cv.y, y);
            h[4*q+2] = fmaf(__expf(Ac[4*q+2] * de), h[4*q+2], dx * bv.z); y = fmaf(h[4*q+2], cv.z, y);
            h[4*q+3] = fmaf(__expf(Ac[4*q+3] * de), h[4*q+3], dx * bv.w); y = fmaf(h[4*q+3], cv.w, y);
        }
        float xcv = g_xc[(size_t)m * DM + d];
        y = fmaf(xcv, Dp, y);
        float res = g_xr[(size_t)m * 2 * DM + DM + d];
        float gate = res / (1.f + __expf(-res));
        float yg = y * gate;
        size_t o = (size_t)m * 2 * DM + d;
        __nv_bfloat16 hh = __float2bfloat16(yg);
        g_A2hi[o] = hh;
        g_A2lo[o] = __float2bfloat16(yg - __bfloat162float(hh));
    }
}

// ---------------- host launcher ----------------
extern "C" void kernel_launch(void* const* d_in, const int* in_sizes, int n_in,
                              void* d_out, int out_size)
{
    const float* x        = (const float*)d_in[0];
    const float* in_w     = (const float*)d_in[1];
    const float* in_b     = (const float*)d_in[2];
    const float* conv_w   = (const float*)d_in[3];
    const float* conv_b   = (const float*)d_in[4];
    const float* xproj_w  = (const float*)d_in[5];
    const float* xproj_b  = (const float*)d_in[6];
    const float* dt_w     = (const float*)d_in[7];
    const float* dt_b     = (const float*)d_in[8];
    const float* A_log    = (const float*)d_in[9];
    const float* D_param  = (const float*)d_in[10];
    const float* out_w    = (const float*)d_in[11];
    const float* out_b    = (const float*)d_in[12];
    const float* skip_w   = (const float*)d_in[13];
    const float* skip_b   = (const float*)d_in[14];
    float* out = (float*)d_out;

    float *p_xr, *p_xc, *p_ssm, *p_delta, *p_dxc;
    __nv_bfloat16 *p_xchi, *p_xclo, *p_dthi, *p_dtlo;
    __nv_bfloat16 *p_A2hi, *p_A2lo, *p_Binhi, *p_Binlo, *p_Bxphi, *p_Bxplo;
    __nv_bfloat16 *p_Bdthi, *p_Bdtlo, *p_B2hi, *p_B2lo;
    cudaGetSymbolAddress((void**)&p_xr,    g_xr);
    cudaGetSymbolAddress((void**)&p_xc,    g_xc);
    cudaGetSymbolAddress((void**)&p_xchi,  g_xchi);
    cudaGetSymbolAddress((void**)&p_xclo,  g_xclo);
    cudaGetSymbolAddress((void**)&p_ssm,   g_ssm);
    cudaGetSymbolAddress((void**)&p_dthi,  g_dthi);
    cudaGetSymbolAddress((void**)&p_dtlo,  g_dtlo);
    cudaGetSymbolAddress((void**)&p_delta, g_delta);
    cudaGetSymbolAddress((void**)&p_dxc,   g_dxc);
    cudaGetSymbolAddress((void**)&p_A2hi,  g_A2hi);
    cudaGetSymbolAddress((void**)&p_A2lo,  g_A2lo);
    cudaGetSymbolAddress((void**)&p_Binhi, g_Binhi);
    cudaGetSymbolAddress((void**)&p_Binlo, g_Binlo);
    cudaGetSymbolAddress((void**)&p_Bxphi, g_Bxphi);
    cudaGetSymbolAddress((void**)&p_Bxplo, g_Bxplo);
    cudaGetSymbolAddress((void**)&p_Bdthi, g_Bdthi);
    cudaGetSymbolAddress((void**)&p_Bdtlo, g_Bdtlo);
    cudaGetSymbolAddress((void**)&p_B2hi,  g_B2hi);
    cudaGetSymbolAddress((void**)&p_B2lo,  g_B2lo);

    cudaFuncSetAttribute(gemm_mma<0>, cudaFuncAttributeMaxDynamicSharedMemorySize, GSMEM);
    cudaFuncSetAttribute(gemm_mma<1>, cudaFuncAttributeMaxDynamicSharedMemorySize, GSMEM);
    cudaFuncSetAttribute(gemm_mma<2>, cudaFuncAttributeMaxDynamicSharedMemorySize, GSMEM);

    // converts
    split_x_A2<<<(MTOT * DM) / 256, 256>>>(x);
    split_pair<<<(2 * DM * DM) / 256, 256>>>(in_w, p_Binhi, p_Binlo, 2 * DM * DM);
    split_pair<<<(SSMW * DM + 255) / 256, 256>>>(xproj_w, p_Bxphi, p_Bxplo, SSMW * DM);
    split_pair<<<(DM * DTRANK) / 256, 256>>>(dt_w, p_Bdthi, p_Bdtlo, DM * DTRANK);
    pack_ws<<<(DM * DM) / 256, 256>>>(out_w, skip_w);

    // 1) in_proj: xr = x @ in_w^T + in_b
    {
        dim3 g(2 * DM / 128, MTOT / 128);
        gemm_mma<0><<<g, 256, GSMEM>>>(p_A2hi + DM, p_A2lo + DM, 2 * DM,
                                       p_Binhi, p_Binlo, DM,
                                       2 * DM, DM / 64, in_b, nullptr,
                                       p_xr, 2 * DM, nullptr, nullptr, nullptr, nullptr);
    }
    // 2) conv + silu
    conv_silu<<<(BSZ * DM * TCH) / 256, 256>>>(conv_w, conv_b);
    // 3) x_proj: ssm = xc @ xproj_w^T + b  (N=96 padded)
    {
        dim3 g(1, MTOT / 128);
        gemm_mma<1><<<g, 256, GSMEM>>>(p_xchi, p_xclo, DM,
                                       p_Bxphi, p_Bxplo, DM,
                                       SSMW, DM / 64, xproj_b, nullptr,
                                       p_ssm, SSMW, nullptr, nullptr, p_dthi, p_dtlo);
    }
    // 4) dt_proj: delta = softplus(dt @ dt_w^T + b); dxc = delta*xc
    {
        dim3 g(DM / 128, MTOT / 128);
        gemm_mma<2><<<g, 256, GSMEM>>>(p_dthi, p_dtlo, DTRANK,
                                       p_Bdthi, p_Bdtlo, DTRANK,
                                       DM, 1, dt_b, nullptr,
                                       p_delta, DM, p_xc, p_dxc, nullptr, nullptr);
    }
    // 5) scan
    scan_passA<<<(BSZ * NCHNK * DM) / 256, 256>>>(A_log);
    scan_combine<<<(BSZ * DM) / 256, 256>>>(A_log);
    scan_passB<<<(BSZ * NCHNK * DM) / 256, 256>>>(A_log, D_param);
    // 6) fused out+skip: out = [y|x] @ [Wout|Wskip]^T + out_b + skip_b
    {
        dim3 g(DM / 128, MTOT / 128);
        gemm_mma<0><<<g, 256, GSMEM>>>(p_A2hi, p_A2lo, 2 * DM,
                                       p_B2hi, p_B2lo, 2 * DM,
                                       DM, 2 * DM / 64, out_b, skip_b,
                                       out, DM, nullptr, nullptr, nullptr, nullptr);
    }
}

// round 4
// speedup vs baseline: 3.4792x; 1.3627x over previous
#include <cuda_runtime.h>
#include <cuda_fp16.h>
#include <math.h>
#include <stdint.h>

// ---------------- problem dims ----------------
#define BSZ    2
#define TLEN   2048
#define DM     1024
#define NST    16
#define DTRANK 64
#define SSMW   96
#define MTOT   (BSZ*TLEN)     // 4096
#define NCHNK  64
#define CLEN   (TLEN/NCHNK)   // 32
#define TCH    16
#define TLCH   (TLEN/TCH)     // 128

// ---------------- device scratch (no allocations) ----------------
__device__ float g_xr   [(size_t)MTOT * 2 * DM];   // in_proj out (x_in | res) fp32
__device__ float g_xc   [(size_t)MTOT * DM];       // conv+silu fp32 (for scan)
__device__ __half g_xch [(size_t)MTOT * DM];       // conv+silu fp16 (GEMM A)
__device__ float g_ssm  [(size_t)MTOT * SSMW];     // x_proj out fp32
__device__ __half g_dth [(size_t)MTOT * DTRANK];   // dt fp16 (GEMM A)
__device__ float g_delta[(size_t)MTOT * DM];       // softplus(dt) fp32
__device__ float g_sp   [(size_t)BSZ * NCHNK * DM];
__device__ float g_hend [(size_t)BSZ * NCHNK * NST * DM];
__device__ float g_hinit[(size_t)BSZ * NCHNK * NST * DM];
// A2 = [y | x] (4096 x 2048) fp16; x half doubles as in_proj A
__device__ __half g_A2h [(size_t)MTOT * 2 * DM];
// fp16 weights
__device__ __half g_Binh[(size_t)2 * DM * DM];
__device__ __half g_Bxph[(size_t)SSMW * DM];
__device__ __half g_Bdth[(size_t)DM * DTRANK];
__device__ __half g_B2h [(size_t)DM * 2 * DM];     // [Wout | Wskip]

// ---------------- helpers ----------------
__device__ __forceinline__ uint32_t smem_u32(const void* p) {
    uint32_t a;
    asm("{ .reg .u64 t; cvta.to.shared.u64 t, %1; cvt.u32.u64 %0, t; }" : "=r"(a) : "l"(p));
    return a;
}
#define SW128(o) ((o) ^ (((o) >> 3) & 0x70))

__device__ __forceinline__ void ldm_x4(uint32_t* r, uint32_t addr) {
    asm volatile("ldmatrix.sync.aligned.m8n8.x4.shared.b16 {%0,%1,%2,%3}, [%4];"
                 : "=r"(r[0]), "=r"(r[1]), "=r"(r[2]), "=r"(r[3]) : "r"(addr));
}
__device__ __forceinline__ void mma_f16(float* d, const uint32_t* a, const uint32_t* b) {
    asm volatile("mma.sync.aligned.m16n8k16.row.col.f32.f16.f16.f32 "
                 "{%0,%1,%2,%3}, {%4,%5,%6,%7}, {%8,%9}, {%0,%1,%2,%3};"
                 : "+f"(d[0]), "+f"(d[1]), "+f"(d[2]), "+f"(d[3])
                 : "r"(a[0]), "r"(a[1]), "r"(a[2]), "r"(a[3]), "r"(b[0]), "r"(b[1]));
}

#define STG    32768               // per stage: A 16KB + B 16KB
#define GSMEM  (4 * STG)           // 131072

// ---------------- HMMA fp16 GEMM: C(128x128 tile) = A(MxK) * B(NxK)^T -------
// MODE 0: C = acc + bias (+ bias2)     (in_proj / out+skip)
// MODE 1: ssm fp32 (ldc=96) + dt fp16  (x_proj)
// MODE 2: delta = softplus(acc+bias)   (dt_proj)
template<int MODE>
__global__ void __launch_bounds__(256, 1)
gemm_mma(const __half* __restrict__ A, int lda,
         const __half* __restrict__ B, int ldb,
         int Ntot, int KT,
         const float* __restrict__ bias, const float* __restrict__ bias2,
         float* __restrict__ C, int ldc,
         __half* __restrict__ dth)
{
    extern __shared__ char smem[];
    const uint32_t sb  = smem_u32(smem);
    const int tid  = threadIdx.x;
    const int wid  = tid >> 5;
    const int lane = tid & 31;
    const int bm   = blockIdx.y * 128;
    const int bn   = blockIdx.x * 128;
    const int wrow = (wid & 3) * 32;   // warp M offset
    const int wcol = (wid >> 2) * 64;  // warp N offset

    float acc[2][8][4];
#pragma unroll
    for (int m = 0; m < 2; m++)
#pragma unroll
        for (int n = 0; n < 8; n++)
#pragma unroll
            for (int v = 0; v < 4; v++) acc[m][n][v] = 0.f;

    auto load_stage = [&](int kt, int s) {
        uint32_t stg = sb + s * STG;
        int koff = kt * 64;
#pragma unroll
        for (int ab = 0; ab < 2; ab++) {
            const __half* base = ab ? B : A;
            const int ld = ab ? ldb : lda;
#pragma unroll
            for (int i = 0; i < 4; i++) {
                int chunk = tid + i * 256;           // 0..1023: 128 rows x 8 16B chunks
                int row = chunk >> 3, c16 = chunk & 7;
                uint32_t dst = stg + ab * 16384 + SW128(row * 128 + c16 * 16);
                int gr = (ab ? bn : bm) + row;
                int sz = 16;
                if (ab && gr >= Ntot) { gr = 0; sz = 0; }
                const __half* src = base + (size_t)gr * ld + koff + c16 * 8;
                asm volatile("cp.async.cg.shared.global [%0], [%1], 16, %2;"
                             :: "r"(dst), "l"(src), "r"(sz) : "memory");
            }
        }
        asm volatile("cp.async.commit_group;" ::: "memory");
    };

    const int g = lane >> 3, r = lane & 7;

    int pf = KT < 3 ? KT : 3;
    for (int s = 0; s < pf; s++) load_stage(s, s);

    for (int kt = 0; kt < KT; kt++) {
        int ahead = KT - kt; if (ahead > 3) ahead = 3;
        if (ahead == 3)      asm volatile("cp.async.wait_group 2;" ::: "memory");
        else if (ahead == 2) asm volatile("cp.async.wait_group 1;" ::: "memory");
        else                 asm volatile("cp.async.wait_group 0;" ::: "memory");
        __syncthreads();
        if (kt + 3 < KT) load_stage(kt + 3, (kt + 3) & 3);

        uint32_t stg = sb + (kt & 3) * STG;
#pragma unroll
        for (int ks = 0; ks < 4; ks++) {
            const int kByte = ks * 32;
            uint32_t a[2][4];
#pragma unroll
            for (int m = 0; m < 2; m++) {
                uint32_t off = SW128((wrow + m * 16 + (g & 1) * 8 + r) * 128 + kByte + (g >> 1) * 16);
                ldm_x4(a[m], stg + off);
            }
            uint32_t b[8][2];
#pragma unroll
            for (int nb = 0; nb < 4; nb++) {
                uint32_t off = SW128((wcol + nb * 16 + (g >> 1) * 8 + r) * 128 + kByte + (g & 1) * 16);
                uint32_t t[4];
                ldm_x4(t, stg + 16384 + off);
                b[nb * 2][0] = t[0]; b[nb * 2][1] = t[1];
                b[nb * 2 + 1][0] = t[2]; b[nb * 2 + 1][1] = t[3];
            }
#pragma unroll
            for (int m = 0; m < 2; m++)
#pragma unroll
                for (int n = 0; n < 8; n++)
                    mma_f16(acc[m][n], a[m], b[n]);
        }
    }
    __syncthreads();

    // stage accumulators through smem for coalesced epilogue
    float* epi = (float*)smem;
#pragma unroll
    for (int m = 0; m < 2; m++)
#pragma unroll
        for (int n = 0; n < 8; n++) {
            int row = wrow + m * 16 + (lane >> 2);
            int col = wcol + n * 8 + (lane & 3) * 2;
            epi[row * 128 + col]           = acc[m][n][0];
            epi[row * 128 + col + 1]       = acc[m][n][1];
            epi[(row + 8) * 128 + col]     = acc[m][n][2];
            epi[(row + 8) * 128 + col + 1] = acc[m][n][3];
        }
    __syncthreads();

    const float4* epi4 = (const float4*)epi;
    if (MODE == 0) {
#pragma unroll 4
        for (int i = 0; i < 16; i++) {
            int e = tid + i * 256;
            int row = e >> 5, c4 = e & 31;
            float4 v = epi4[e];
            int n = bn + c4 * 4;
            v.x += bias[n + 0]; v.y += bias[n + 1]; v.z += bias[n + 2]; v.w += bias[n + 3];
            if (bias2) {
                v.x += bias2[n + 0]; v.y += bias2[n + 1]; v.z += bias2[n + 2]; v.w += bias2[n + 3];
            }
            *(float4*)(C + (size_t)(bm + row) * ldc + n) = v;
        }
    } else if (MODE == 2) {
#pragma unroll 4
        for (int i = 0; i < 16; i++) {
            int e = tid + i * 256;
            int row = e >> 5, c4 = e & 31;
            float4 v = epi4[e];
            int n = bn + c4 * 4;
            v.x += bias[n + 0]; v.y += bias[n + 1]; v.z += bias[n + 2]; v.w += bias[n + 3];
            float4 sp;
            sp.x = (v.x > 20.f) ? v.x : log1pf(expf(v.x));
            sp.y = (v.y > 20.f) ? v.y : log1pf(expf(v.y));
            sp.z = (v.z > 20.f) ? v.z : log1pf(expf(v.z));
            sp.w = (v.w > 20.f) ? v.w : log1pf(expf(v.w));
            *(float4*)(C + (size_t)(bm + row) * DM + n) = sp;
        }
    } else { // MODE 1: x_proj, Ntot = 96
        for (int i = 0; i < 16; i++) {
            int e = tid + i * 256;
            int row = e >> 5, c4 = e & 31;
            if (c4 >= 24) continue;
            float4 v = epi4[e];
            int n = c4 * 4;
            v.x += bias[n + 0]; v.y += bias[n + 1]; v.z += bias[n + 2]; v.w += bias[n + 3];
            *(float4*)(C + (size_t)(bm + row) * SSMW + n) = v;
            if (c4 < 16) {
                size_t di = (size_t)(bm + row) * DTRANK + n;
                __half2* dst = (__half2*)(dth + di);
                dst[0] = __floats2half2_rn(v.x, v.y);
                dst[1] = __floats2half2_rn(v.z, v.w);
            }
        }
    }
}

// ---------------- fused converts (single launch) ----------------
__global__ void prep_all(const float* __restrict__ x, const float* __restrict__ in_w,
                         const float* __restrict__ xproj_w, const float* __restrict__ dt_w,
                         const float* __restrict__ out_w, const float* __restrict__ skip_w)
{
    const int NX  = MTOT * DM;
    const int NIN = 2 * DM * DM;
    const int NXP = SSMW * DM;
    const int NDT = DM * DTRANK;
    const int NO  = DM * DM;
    int i = blockIdx.x * 256 + threadIdx.x;
    if (i < NX) {
        int m = i >> 10, c = i & 1023;
        g_A2h[(size_t)m * 2048 + 1024 + c] = __float2half(x[i]);
        return;
    }
    i -= NX;
    if (i < NIN) { g_Binh[i] = __float2half(in_w[i]); return; }
    i -= NIN;
    if (i < NXP) { g_Bxph[i] = __float2half(xproj_w[i]); return; }
    i -= NXP;
    if (i < NDT) { g_Bdth[i] = __float2half(dt_w[i]); return; }
    i -= NDT;
    if (i < NO) {
        int m = i >> 10, c = i & 1023;
        size_t o = (size_t)m * 2048;
        g_B2h[o + c]        = __float2half(out_w[i]);
        g_B2h[o + 1024 + c] = __float2half(skip_w[i]);
    }
}

// ---------------- depthwise causal conv (k=4) + silu ------------------------
__global__ void conv_silu(const float* __restrict__ cw, const float* __restrict__ cb)
{
    int gid = blockIdx.x * blockDim.x + threadIdx.x;
    if (gid >= BSZ * DM * TCH) return;
    int d  = gid % DM;
    int r  = gid / DM;
    int tc = r % TCH;
    int b  = r / TCH;

    float w0 = cw[d * 4 + 0], w1 = cw[d * 4 + 1], w2 = cw[d * 4 + 2], w3 = cw[d * 4 + 3];
    float bias = cb[d];
    int t0 = tc * TLCH;

    const float* xin = g_xr + (size_t)b * TLEN * 2 * DM + d;
    float xm3 = (t0 - 3 >= 0) ? xin[(size_t)(t0 - 3) * 2 * DM] : 0.f;
    float xm2 = (t0 - 2 >= 0) ? xin[(size_t)(t0 - 2) * 2 * DM] : 0.f;
    float xm1 = (t0 - 1 >= 0) ? xin[(size_t)(t0 - 1) * 2 * DM] : 0.f;

    for (int i = 0; i < TLCH; i++) {
        int t = t0 + i;
        float x0 = xin[(size_t)t * 2 * DM];
        float a = bias;
        a = fmaf(w0, xm3, a); a = fmaf(w1, xm2, a);
        a = fmaf(w2, xm1, a); a = fmaf(w3, x0, a);
        float s = a / (1.f + __expf(-a));
        size_t o = (size_t)(b * TLEN + t) * DM + d;
        g_xc[o]  = s;
        g_xch[o] = __float2half(s);
        xm3 = xm2; xm2 = xm1; xm1 = x0;
    }
}

// ---------------- dA powers: r^(n+1), log-depth, with general fallback ------
struct AConsts {
    float Ac[NST];
    float Ac0;
    bool  geom;
};
__device__ __forceinline__ AConsts load_aconsts(const float* A_log) {
    AConsts a;
#pragma unroll
    for (int n = 0; n < NST; n++) a.Ac[n] = -__expf(A_log[n]);
    a.Ac0 = a.Ac[0];
    a.geom = true;
#pragma unroll
    for (int n = 0; n < NST; n++)
        a.geom = a.geom && (fabsf(a.Ac[n] - (float)(n + 1) * a.Ac0) <= 1e-5f * fabsf(a.Ac[n]));
    return a;
}
__device__ __forceinline__ void da_powers(const AConsts& a, float de, float* pw) {
    if (a.geom) {
        float r = __expf(a.Ac0 * de);
        pw[0] = r;
        pw[1] = pw[0] * pw[0];
        pw[2] = pw[1] * pw[0];
        pw[3] = pw[1] * pw[1];
        pw[4] = pw[2] * pw[1];
        pw[5] = pw[2] * pw[2];
        pw[6] = pw[3] * pw[2];
        pw[7] = pw[3] * pw[3];
        pw[8] = pw[4] * pw[3];
        pw[9] = pw[4] * pw[4];
        pw[10] = pw[5] * pw[4];
        pw[11] = pw[5] * pw[5];
        pw[12] = pw[6] * pw[5];
        pw[13] = pw[6] * pw[6];
        pw[14] = pw[7] * pw[6];
        pw[15] = pw[7] * pw[7];
    } else {
#pragma unroll
        for (int n = 0; n < NST; n++) pw[n] = __expf(a.Ac[n] * de);
    }
}

// ---------------- chunked selective scan ----------------
__global__ void scan_passA(const float* __restrict__ A_log)
{
    int gid = blockIdx.x * blockDim.x + threadIdx.x;
    if (gid >= BSZ * NCHNK * DM) return;
    int d = gid % DM;
    int r = gid / DM;
    int c = r % NCHNK;
    int b = r / NCHNK;

    AConsts a = load_aconsts(A_log);
    float h[NST];
#pragma unroll
    for (int n = 0; n < NST; n++) h[n] = 0.f;
    float sp = 0.f;

    int m0 = b * TLEN + c * CLEN;
    for (int i = 0; i < CLEN; i++) {
        int m = m0 + i;
        float de = g_delta[(size_t)m * DM + d];
        float dx = de * g_xc[(size_t)m * DM + d];
        sp += de;
        float pw[NST];
        da_powers(a, de, pw);
        const float4* bp = (const float4*)(g_ssm + (size_t)m * SSMW + DTRANK);
#pragma unroll
        for (int q = 0; q < 4; q++) {
            float4 bv = bp[q];
            h[4*q+0] = fmaf(pw[4*q+0], h[4*q+0], dx * bv.x);
            h[4*q+1] = fmaf(pw[4*q+1], h[4*q+1], dx * bv.y);
            h[4*q+2] = fmaf(pw[4*q+2], h[4*q+2], dx * bv.z);
            h[4*q+3] = fmaf(pw[4*q+3], h[4*q+3], dx * bv.w);
        }
    }
    g_sp[(size_t)(b * NCHNK + c) * DM + d] = sp;
    size_t base = (size_t)((b * NCHNK + c) * NST) * DM + d;
#pragma unroll
    for (int n = 0; n < NST; n++) g_hend[base + (size_t)n * DM] = h[n];
}

__global__ void scan_combine(const float* __restrict__ A_log)
{
    int gid = blockIdx.x * blockDim.x + threadIdx.x;
    if (gid >= BSZ * DM) return;
    int d = gid % DM;
    int b = gid / DM;

    AConsts a = load_aconsts(A_log);
    float h[NST];
#pragma unroll
    for (int n = 0; n < NST; n++) h[n] = 0.f;

    for (int c = 0; c < NCHNK; c++) {
        size_t base = (size_t)((b * NCHNK + c) * NST) * DM + d;
        float sp = g_sp[(size_t)(b * NCHNK + c) * DM + d];
        float pw[NST];
        da_powers(a, sp, pw);
#pragma unroll
        for (int n = 0; n < NST; n++) {
            g_hinit[base + (size_t)n * DM] = h[n];
            h[n] = fmaf(pw[n], h[n], g_hend[base + (size_t)n * DM]);
        }
    }
}

__global__ void scan_passB(const float* __restrict__ A_log, const float* __restrict__ D_param)
{
    int gid = blockIdx.x * blockDim.x + threadIdx.x;
    if (gid >= BSZ * NCHNK * DM) return;
    int d = gid % DM;
    int r = gid / DM;
    int c = r % NCHNK;
    int b = r / NCHNK;

    AConsts a = load_aconsts(A_log);
    float h[NST];
    size_t base = (size_t)((b * NCHNK + c) * NST) * DM + d;
#pragma unroll
    for (int n = 0; n < NST; n++) h[n] = g_hinit[base + (size_t)n * DM];

    float Dp = D_param[d];
    int m0 = b * TLEN + c * CLEN;

    for (int i = 0; i < CLEN; i++) {
        int m = m0 + i;
        float de = g_delta[(size_t)m * DM + d];
        float xcv = g_xc[(size_t)m * DM + d];
        float dx = de * xcv;
        float pw[NST];
        da_powers(a, de, pw);
        const float4* bp = (const float4*)(g_ssm + (size_t)m * SSMW + DTRANK);
        const float4* cp = (const float4*)(g_ssm + (size_t)m * SSMW + DTRANK + NST);
        float y = 0.f;
#pragma unroll
        for (int q = 0; q < 4; q++) {
            float4 bv = bp[q];
            float4 cv = cp[q];
            h[4*q+0] = fmaf(pw[4*q+0], h[4*q+0], dx * bv.x); y = fmaf(h[4*q+0], cv.x, y);
            h[4*q+1] = fmaf(pw[4*q+1], h[4*q+1], dx * bv.y); y = fmaf(h[4*q+1], cv.y, y);
            h[4*q+2] = fmaf(pw[4*q+2], h[4*q+2], dx * bv.z); y = fmaf(h[4*q+2], cv.z, y);
            h[4*q+3] = fmaf(pw[4*q+3], h[4*q+3], dx * bv.w); y = fmaf(h[4*q+3], cv.w, y);
        }
        y = fmaf(xcv, Dp, y);
        float res = g_xr[(size_t)m * 2 * DM + DM + d];
        float gate = res / (1.f + __expf(-res));
        g_A2h[(size_t)m * 2 * DM + d] = __float2half(y * gate);
    }
}

// ---------------- host launcher ---------------------------------------------
extern "C" void kernel_launch(void* const* d_in, const int* in_sizes, int n_in,
                              void* d_out, int out_size)
{
    const float* x        = (const float*)d_in[0];
    const float* in_w     = (const float*)d_in[1];
    const float* in_b     = (const float*)d_in[2];
    const float* conv_w   = (const float*)d_in[3];
    const float* conv_b   = (const float*)d_in[4];
    const float* xproj_w  = (const float*)d_in[5];
    const float* xproj_b  = (const float*)d_in[6];
    const float* dt_w     = (const float*)d_in[7];
    const float* dt_b     = (const float*)d_in[8];
    const float* A_log    = (const float*)d_in[9];
    const float* D_param  = (const float*)d_in[10];
    const float* out_w    = (const float*)d_in[11];
    const float* out_b    = (const float*)d_in[12];
    const float* skip_w   = (const float*)d_in[13];
    const float* skip_b   = (const float*)d_in[14];
    float* out = (float*)d_out;

    float *p_xr, *p_ssm, *p_delta;
    __half *p_xch, *p_dth, *p_A2h, *p_Binh, *p_Bxph, *p_Bdth, *p_B2h;
    cudaGetSymbolAddress((void**)&p_xr,    g_xr);
    cudaGetSymbolAddress((void**)&p_ssm,   g_ssm);
    cudaGetSymbolAddress((void**)&p_delta, g_delta);
    cudaGetSymbolAddress((void**)&p_xch,   g_xch);
    cudaGetSymbolAddress((void**)&p_dth,   g_dth);
    cudaGetSymbolAddress((void**)&p_A2h,   g_A2h);
    cudaGetSymbolAddress((void**)&p_Binh,  g_Binh);
    cudaGetSymbolAddress((void**)&p_Bxph,  g_Bxph);
    cudaGetSymbolAddress((void**)&p_Bdth,  g_Bdth);
    cudaGetSymbolAddress((void**)&p_B2h,   g_B2h);

    cudaFuncSetAttribute(gemm_mma<0>, cudaFuncAttributeMaxDynamicSharedMemorySize, GSMEM);
    cudaFuncSetAttribute(gemm_mma<1>, cudaFuncAttributeMaxDynamicSharedMemorySize, GSMEM);
    cudaFuncSetAttribute(gemm_mma<2>, cudaFuncAttributeMaxDynamicSharedMemorySize, GSMEM);

    // 0) all converts in one launch
    {
        const int total = MTOT * DM + 2 * DM * DM + SSMW * DM + DM * DTRANK + DM * DM;
        prep_all<<<(total + 255) / 256, 256>>>(x, in_w, xproj_w, dt_w, out_w, skip_w);
    }
    // 1) in_proj: xr = x @ in_w^T + in_b
    {
        dim3 g(2 * DM / 128, MTOT / 128);
        gemm_mma<0><<<g, 256, GSMEM>>>(p_A2h + DM, 2 * DM, p_Binh, DM,
                                       2 * DM, DM / 64, in_b, nullptr,
                                       p_xr, 2 * DM, nullptr);
    }
    // 2) conv + silu
    conv_silu<<<(BSZ * DM * TCH) / 256, 256>>>(conv_w, conv_b);
    // 3) x_proj: ssm = xc @ xproj_w^T + b  (N=96 padded)
    {
        dim3 g(1, MTOT / 128);
        gemm_mma<1><<<g, 256, GSMEM>>>(p_xch, DM, p_Bxph, DM,
                                       SSMW, DM / 64, xproj_b, nullptr,
                                       p_ssm, SSMW, p_dth);
    }
    // 4) dt_proj: delta = softplus(dt @ dt_w^T + b)
    {
        dim3 g(DM / 128, MTOT / 128);
        gemm_mma<2><<<g, 256, GSMEM>>>(p_dth, DTRANK, p_Bdth, DTRANK,
                                       DM, 1, dt_b, nullptr,
                                       p_delta, DM, nullptr);
    }
    // 5) scan
    scan_passA<<<(BSZ * NCHNK * DM) / 256, 256>>>(A_log);
    scan_combine<<<(BSZ * DM) / 256, 256>>>(A_log);
    scan_passB<<<(BSZ * NCHNK * DM) / 256, 256>>>(A_log, D_param);
    // 6) fused out+skip: out = [y|x] @ [Wout|Wskip]^T + out_b + skip_b
    {
        dim3 g(DM / 128, MTOT / 128);
        gemm_mma<0><<<g, 256, GSMEM>>>(p_A2h, 2 * DM, p_B2h, 2 * DM,
                                       DM, 2 * DM / 64, out_b, skip_b,
                                       out, DM, nullptr);
    }
}

// round 5
// speedup vs baseline: 3.8031x; 1.0931x over previous
#include <cuda_runtime.h>
#include <cuda_fp16.h>
#include <math.h>
#include <stdint.h>

// ---------------- problem dims ----------------
#define BSZ    2
#define TLEN   2048
#define DM     1024
#define NST    16
#define DTRANK 64
#define SSMW   96
#define MTOT   (BSZ*TLEN)     // 4096
#define NCHNK  64
#define CLEN   (TLEN/NCHNK)   // 32
#define TCH    16
#define TLCH   (TLEN/TCH)     // 128

// ---------------- device scratch (no allocations) ----------------
__device__ float g_xr   [(size_t)MTOT * 2 * DM];
__device__ float g_xc   [(size_t)MTOT * DM];
__device__ __half g_xch [(size_t)MTOT * DM];
__device__ float g_ssm  [(size_t)MTOT * SSMW];
__device__ __half g_dth [(size_t)MTOT * DTRANK];
__device__ float g_delta[(size_t)MTOT * DM];
__device__ float g_sp   [(size_t)BSZ * NCHNK * DM];
__device__ float g_hend [(size_t)BSZ * NCHNK * NST * DM];
__device__ float g_hinit[(size_t)BSZ * NCHNK * NST * DM];
__device__ __half g_A2h [(size_t)MTOT * 2 * DM];   // [y | x]
__device__ __half g_Binh[(size_t)2 * DM * DM];
__device__ __half g_Bxph[(size_t)SSMW * DM];
__device__ __half g_Bdth[(size_t)DM * DTRANK];
__device__ __half g_B2h [(size_t)DM * 2 * DM];     // [Wout | Wskip]

// ---------------- helpers ----------------
__device__ __forceinline__ uint32_t smem_u32(const void* p) {
    uint32_t a;
    asm("{ .reg .u64 t; cvta.to.shared.u64 t, %1; cvt.u32.u64 %0, t; }" : "=r"(a) : "l"(p));
    return a;
}
#define SW128(o) ((o) ^ (((o) >> 3) & 0x70))

__device__ __forceinline__ void ldm_x4(uint32_t* r, uint32_t addr) {
    asm volatile("ldmatrix.sync.aligned.m8n8.x4.shared.b16 {%0,%1,%2,%3}, [%4];"
                 : "=r"(r[0]), "=r"(r[1]), "=r"(r[2]), "=r"(r[3]) : "r"(addr));
}
__device__ __forceinline__ void mma_f16(float* d, const uint32_t* a, const uint32_t* b) {
    asm volatile("mma.sync.aligned.m16n8k16.row.col.f32.f16.f16.f32 "
                 "{%0,%1,%2,%3}, {%4,%5,%6,%7}, {%8,%9}, {%0,%1,%2,%3};"
                 : "+f"(d[0]), "+f"(d[1]), "+f"(d[2]), "+f"(d[3])
                 : "r"(a[0]), "r"(a[1]), "r"(a[2]), "r"(a[3]), "r"(b[0]), "r"(b[1]));
}

// ---------------- HMMA fp16 GEMM, tile BM x 128, 3-stage cp.async ----------
// MODE 0: C = acc + bias (+ bias2)
// MODE 1: ssm fp32 (ldc=96) + dt fp16
// MODE 2: delta = softplus(acc+bias)
// BM in {128, 64}. Stage: A(BM x 64) + B(128 x 64) halves, SW128 rows.
template<int MODE, int BM>
__global__ void __launch_bounds__(256, 2)
gemm_mma(const __half* __restrict__ A, int lda,
         const __half* __restrict__ B, int ldb,
         int Ntot, int KT,
         const float* __restrict__ bias, const float* __restrict__ bias2,
         float* __restrict__ C, int ldc,
         __half* __restrict__ dth)
{
    constexpr int ABYTES = BM * 128;          // A tile bytes
    constexpr int STG    = ABYTES + 16384;    // stage bytes
    constexpr int NT     = (BM == 128) ? 8 : 4;  // n8 tiles per warp

    extern __shared__ char smem[];
    const uint32_t sb  = smem_u32(smem);
    const int tid  = threadIdx.x;
    const int wid  = tid >> 5;
    const int lane = tid & 31;
    const int bm   = blockIdx.y * BM;
    const int bn   = blockIdx.x * 128;
    const int wrow = (BM == 128) ? (wid & 3) * 32 : (wid & 1) * 32;
    const int wcol = (BM == 128) ? (wid >> 2) * 64 : (wid >> 1) * 32;

    float acc[2][NT][4];
#pragma unroll
    for (int m = 0; m < 2; m++)
#pragma unroll
        for (int n = 0; n < NT; n++)
#pragma unroll
            for (int v = 0; v < 4; v++) acc[m][n][v] = 0.f;

    // per-thread load assignment (16B chunks): A has BM*8 chunks, B has 1024
    auto load_stage = [&](int kt, int s) {
        uint32_t stg = sb + s * STG;
        int koff = kt * 64;
        // A chunks
#pragma unroll
        for (int i = 0; i < BM / 32; i++) {
            int chunk = tid + i * 256;
            int row = chunk >> 3, c16 = chunk & 7;
            uint32_t dst = stg + SW128(row * 128 + c16 * 16);
            const __half* src = A + (size_t)(bm + row) * lda + koff + c16 * 8;
            asm volatile("cp.async.cg.shared.global [%0], [%1], 16;"
                         :: "r"(dst), "l"(src) : "memory");
        }
        // B chunks
#pragma unroll
        for (int i = 0; i < 4; i++) {
            int chunk = tid + i * 256;
            int row = chunk >> 3, c16 = chunk & 7;
            uint32_t dst = stg + ABYTES + SW128(row * 128 + c16 * 16);
            int gr = bn + row;
            int sz = 16;
            if (gr >= Ntot) { gr = 0; sz = 0; }
            const __half* src = B + (size_t)gr * ldb + koff + c16 * 8;
            asm volatile("cp.async.cg.shared.global [%0], [%1], 16, %2;"
                         :: "r"(dst), "l"(src), "r"(sz) : "memory");
        }
        asm volatile("cp.async.commit_group;" ::: "memory");
    };

    const int g = lane >> 3, r = lane & 7;

    int pf = KT < 2 ? KT : 2;
    for (int s = 0; s < pf; s++) load_stage(s, s);

    for (int kt = 0; kt < KT; kt++) {
        if (kt + 1 < KT) asm volatile("cp.async.wait_group 1;" ::: "memory");
        else             asm volatile("cp.async.wait_group 0;" ::: "memory");
        __syncthreads();
        if (kt + 2 < KT) load_stage(kt + 2, (kt + 2) % 3);

        uint32_t stg = sb + (kt % 3) * STG;
#pragma unroll
        for (int ks = 0; ks < 4; ks++) {
            const int kByte = ks * 32;
            uint32_t a[2][4];
#pragma unroll
            for (int m = 0; m < 2; m++) {
                uint32_t off = SW128((wrow + m * 16 + (g & 1) * 8 + r) * 128 + kByte + (g >> 1) * 16);
                ldm_x4(a[m], stg + off);
            }
            uint32_t b[NT][2];
#pragma unroll
            for (int nb = 0; nb < NT / 2; nb++) {
                uint32_t off = SW128((wcol + nb * 16 + (g >> 1) * 8 + r) * 128 + kByte + (g & 1) * 16);
                uint32_t t[4];
                ldm_x4(t, stg + ABYTES + off);
                b[nb * 2][0] = t[0]; b[nb * 2][1] = t[1];
                b[nb * 2 + 1][0] = t[2]; b[nb * 2 + 1][1] = t[3];
            }
#pragma unroll
            for (int m = 0; m < 2; m++)
#pragma unroll
                for (int n = 0; n < NT; n++)
                    mma_f16(acc[m][n], a[m], b[n]);
        }
    }
    __syncthreads();

    // epilogue staging
    float* epi = (float*)smem;
#pragma unroll
    for (int m = 0; m < 2; m++)
#pragma unroll
        for (int n = 0; n < NT; n++) {
            int row = wrow + m * 16 + (lane >> 2);
            int col = wcol + n * 8 + (lane & 3) * 2;
            epi[row * 128 + col]           = acc[m][n][0];
            epi[row * 128 + col + 1]       = acc[m][n][1];
            epi[(row + 8) * 128 + col]     = acc[m][n][2];
            epi[(row + 8) * 128 + col + 1] = acc[m][n][3];
        }
    __syncthreads();

    const float4* epi4 = (const float4*)epi;
    constexpr int EIT = BM / 8;
    if (MODE == 0) {
#pragma unroll 4
        for (int i = 0; i < EIT; i++) {
            int e = tid + i * 256;
            int row = e >> 5, c4 = e & 31;
            float4 v = epi4[e];
            int n = bn + c4 * 4;
            v.x += bias[n + 0]; v.y += bias[n + 1]; v.z += bias[n + 2]; v.w += bias[n + 3];
            if (bias2) {
                v.x += bias2[n + 0]; v.y += bias2[n + 1]; v.z += bias2[n + 2]; v.w += bias2[n + 3];
            }
            *(float4*)(C + (size_t)(bm + row) * ldc + n) = v;
        }
    } else if (MODE == 2) {
#pragma unroll 4
        for (int i = 0; i < EIT; i++) {
            int e = tid + i * 256;
            int row = e >> 5, c4 = e & 31;
            float4 v = epi4[e];
            int n = bn + c4 * 4;
            v.x += bias[n + 0]; v.y += bias[n + 1]; v.z += bias[n + 2]; v.w += bias[n + 3];
            float4 sp;
            sp.x = (v.x > 20.f) ? v.x : log1pf(expf(v.x));
            sp.y = (v.y > 20.f) ? v.y : log1pf(expf(v.y));
            sp.z = (v.z > 20.f) ? v.z : log1pf(expf(v.z));
            sp.w = (v.w > 20.f) ? v.w : log1pf(expf(v.w));
            *(float4*)(C + (size_t)(bm + row) * DM + n) = sp;
        }
    } else { // MODE 1: x_proj, Ntot = 96
        for (int i = 0; i < EIT; i++) {
            int e = tid + i * 256;
            int row = e >> 5, c4 = e & 31;
            if (c4 >= 24) continue;
            float4 v = epi4[e];
            int n = c4 * 4;
            v.x += bias[n + 0]; v.y += bias[n + 1]; v.z += bias[n + 2]; v.w += bias[n + 3];
            *(float4*)(C + (size_t)(bm + row) * SSMW + n) = v;
            if (c4 < 16) {
                size_t di = (size_t)(bm + row) * DTRANK + n;
                __half2* dst = (__half2*)(dth + di);
                dst[0] = __floats2half2_rn(v.x, v.y);
                dst[1] = __floats2half2_rn(v.z, v.w);
            }
        }
    }
}

#define GSMEM128 (3 * (128 * 128 + 16384))   // 98304
#define GSMEM64  (3 * (64 * 128 + 16384))    // 73728

// ---------------- fused converts ----------------
__global__ void prep_all(const float* __restrict__ x, const float* __restrict__ in_w,
                         const float* __restrict__ xproj_w, const float* __restrict__ dt_w,
                         const float* __restrict__ out_w, const float* __restrict__ skip_w)
{
    const int NX  = MTOT * DM;
    const int NIN = 2 * DM * DM;
    const int NXP = SSMW * DM;
    const int NDT = DM * DTRANK;
    const int NO  = DM * DM;
    int i = blockIdx.x * 256 + threadIdx.x;
    if (i < NX) {
        int m = i >> 10, c = i & 1023;
        g_A2h[(size_t)m * 2048 + 1024 + c] = __float2half(x[i]);
        return;
    }
    i -= NX;
    if (i < NIN) { g_Binh[i] = __float2half(in_w[i]); return; }
    i -= NIN;
    if (i < NXP) { g_Bxph[i] = __float2half(xproj_w[i]); return; }
    i -= NXP;
    if (i < NDT) { g_Bdth[i] = __float2half(dt_w[i]); return; }
    i -= NDT;
    if (i < NO) {
        int m = i >> 10, c = i & 1023;
        size_t o = (size_t)m * 2048;
        g_B2h[o + c]        = __float2half(out_w[i]);
        g_B2h[o + 1024 + c] = __float2half(skip_w[i]);
    }
}

// ---------------- depthwise causal conv (k=4) + silu ------------------------
__global__ void conv_silu(const float* __restrict__ cw, const float* __restrict__ cb)
{
    int gid = blockIdx.x * blockDim.x + threadIdx.x;
    if (gid >= BSZ * DM * TCH) return;
    int d  = gid % DM;
    int r  = gid / DM;
    int tc = r % TCH;
    int b  = r / TCH;

    float w0 = cw[d * 4 + 0], w1 = cw[d * 4 + 1], w2 = cw[d * 4 + 2], w3 = cw[d * 4 + 3];
    float bias = cb[d];
    int t0 = tc * TLCH;

    const float* xin = g_xr + (size_t)b * TLEN * 2 * DM + d;
    float xm3 = (t0 - 3 >= 0) ? xin[(size_t)(t0 - 3) * 2 * DM] : 0.f;
    float xm2 = (t0 - 2 >= 0) ? xin[(size_t)(t0 - 2) * 2 * DM] : 0.f;
    float xm1 = (t0 - 1 >= 0) ? xin[(size_t)(t0 - 1) * 2 * DM] : 0.f;

    for (int i = 0; i < TLCH; i++) {
        int t = t0 + i;
        float x0 = xin[(size_t)t * 2 * DM];
        float a = bias;
        a = fmaf(w0, xm3, a); a = fmaf(w1, xm2, a);
        a = fmaf(w2, xm1, a); a = fmaf(w3, x0, a);
        float s = a / (1.f + __expf(-a));
        size_t o = (size_t)(b * TLEN + t) * DM + d;
        g_xc[o]  = s;
        g_xch[o] = __float2half(s);
        xm3 = xm2; xm2 = xm1; xm1 = x0;
    }
}

// ---------------- dA powers ----------------
struct AConsts {
    float Ac[NST];
    float Ac0;
    bool  geom;
};
__device__ __forceinline__ AConsts load_aconsts(const float* A_log) {
    AConsts a;
#pragma unroll
    for (int n = 0; n < NST; n++) a.Ac[n] = -__expf(A_log[n]);
    a.Ac0 = a.Ac[0];
    a.geom = true;
#pragma unroll
    for (int n = 0; n < NST; n++)
        a.geom = a.geom && (fabsf(a.Ac[n] - (float)(n + 1) * a.Ac0) <= 1e-5f * fabsf(a.Ac[n]));
    return a;
}
__device__ __forceinline__ void da_powers(const AConsts& a, float de, float* pw) {
    if (a.geom) {
        float r = __expf(a.Ac0 * de);
        pw[0] = r;
        pw[1] = pw[0] * pw[0];  pw[2] = pw[1] * pw[0];  pw[3] = pw[1] * pw[1];
        pw[4] = pw[2] * pw[1];  pw[5] = pw[2] * pw[2];  pw[6] = pw[3] * pw[2];
        pw[7] = pw[3] * pw[3];  pw[8] = pw[4] * pw[3];  pw[9] = pw[4] * pw[4];
        pw[10] = pw[5] * pw[4]; pw[11] = pw[5] * pw[5]; pw[12] = pw[6] * pw[5];
        pw[13] = pw[6] * pw[6]; pw[14] = pw[7] * pw[6]; pw[15] = pw[7] * pw[7];
    } else {
#pragma unroll
        for (int n = 0; n < NST; n++) pw[n] = __expf(a.Ac[n] * de);
    }
}

// ---------------- chunked selective scan ----------------
__global__ void scan_passA(const float* __restrict__ A_log)
{
    int gid = blockIdx.x * blockDim.x + threadIdx.x;
    if (gid >= BSZ * NCHNK * DM) return;
    int d = gid % DM;
    int r = gid / DM;
    int c = r % NCHNK;
    int b = r / NCHNK;

    AConsts a = load_aconsts(A_log);
    float h[NST];
#pragma unroll
    for (int n = 0; n < NST; n++) h[n] = 0.f;
    float sp = 0.f;

    int m0 = b * TLEN + c * CLEN;
    for (int i = 0; i < CLEN; i++) {
        int m = m0 + i;
        float de = g_delta[(size_t)m * DM + d];
        float dx = de * g_xc[(size_t)m * DM + d];
        sp += de;
        float pw[NST];
        da_powers(a, de, pw);
        const float4* bp = (const float4*)(g_ssm + (size_t)m * SSMW + DTRANK);
#pragma unroll
        for (int q = 0; q < 4; q++) {
            float4 bv = bp[q];
            h[4*q+0] = fmaf(pw[4*q+0], h[4*q+0], dx * bv.x);
            h[4*q+1] = fmaf(pw[4*q+1], h[4*q+1], dx * bv.y);
            h[4*q+2] = fmaf(pw[4*q+2], h[4*q+2], dx * bv.z);
            h[4*q+3] = fmaf(pw[4*q+3], h[4*q+3], dx * bv.w);
        }
    }
    g_sp[(size_t)(b * NCHNK + c) * DM + d] = sp;
    size_t base = (size_t)((b * NCHNK + c) * NST) * DM + d;
#pragma unroll
    for (int n = 0; n < NST; n++) g_hend[base + (size_t)n * DM] = h[n];
}

__global__ void scan_combine(const float* __restrict__ A_log)
{
    int gid = blockIdx.x * blockDim.x + threadIdx.x;
    if (gid >= BSZ * DM) return;
    int d = gid % DM;
    int b = gid / DM;

    AConsts a = load_aconsts(A_log);
    float h[NST];
#pragma unroll
    for (int n = 0; n < NST; n++) h[n] = 0.f;

    for (int c = 0; c < NCHNK; c++) {
        size_t base = (size_t)((b * NCHNK + c) * NST) * DM + d;
        float sp = g_sp[(size_t)(b * NCHNK + c) * DM + d];
        float pw[NST];
        da_powers(a, sp, pw);
#pragma unroll
        for (int n = 0; n < NST; n++) {
            g_hinit[base + (size_t)n * DM] = h[n];
            h[n] = fmaf(pw[n], h[n], g_hend[base + (size_t)n * DM]);
        }
    }
}

__global__ void scan_passB(const float* __restrict__ A_log, const float* __restrict__ D_param)
{
    int gid = blockIdx.x * blockDim.x + threadIdx.x;
    if (gid >= BSZ * NCHNK * DM) return;
    int d = gid % DM;
    int r = gid / DM;
    int c = r % NCHNK;
    int b = r / NCHNK;

    AConsts a = load_aconsts(A_log);
    float h[NST];
    size_t base = (size_t)((b * NCHNK + c) * NST) * DM + d;
#pragma unroll
    for (int n = 0; n < NST; n++) h[n] = g_hinit[base + (size_t)n * DM];

    float Dp = D_param[d];
    int m0 = b * TLEN + c * CLEN;

    for (int i = 0; i < CLEN; i++) {
        int m = m0 + i;
        float de = g_delta[(size_t)m * DM + d];
        float xcv = g_xc[(size_t)m * DM + d];
        float dx = de * xcv;
        float pw[NST];
        da_powers(a, de, pw);
        const float4* bp = (const float4*)(g_ssm + (size_t)m * SSMW + DTRANK);
        const float4* cp = (const float4*)(g_ssm + (size_t)m * SSMW + DTRANK + NST);
        float y = 0.f;
#pragma unroll
        for (int q = 0; q < 4; q++) {
            float4 bv = bp[q];
            float4 cv = cp[q];
            h[4*q+0] = fmaf(pw[4*q+0], h[4*q+0], dx * bv.x); y = fmaf(h[4*q+0], cv.x, y);
            h[4*q+1] = fmaf(pw[4*q+1], h[4*q+1], dx * bv.y); y = fmaf(h[4*q+1], cv.y, y);
            h[4*q+2] = fmaf(pw[4*q+2], h[4*q+2], dx * bv.z); y = fmaf(h[4*q+2], cv.z, y);
            h[4*q+3] = fmaf(pw[4*q+3], h[4*q+3], dx * bv.w); y = fmaf(h[4*q+3], cv.w, y);
        }
        y = fmaf(xcv, Dp, y);
        float res = g_xr[(size_t)m * 2 * DM + DM + d];
        float gate = res / (1.f + __expf(-res));
        g_A2h[(size_t)m * 2 * DM + d] = __float2half(y * gate);
    }
}

// ---------------- host launcher ---------------------------------------------
extern "C" void kernel_launch(void* const* d_in, const int* in_sizes, int n_in,
                              void* d_out, int out_size)
{
    const float* x        = (const float*)d_in[0];
    const float* in_w     = (const float*)d_in[1];
    const float* in_b     = (const float*)d_in[2];
    const float* conv_w   = (const float*)d_in[3];
    const float* conv_b   = (const float*)d_in[4];
    const float* xproj_w  = (const float*)d_in[5];
    const float* xproj_b  = (const float*)d_in[6];
    const float* dt_w     = (const float*)d_in[7];
    const float* dt_b     = (const float*)d_in[8];
    const float* A_log    = (const float*)d_in[9];
    const float* D_param  = (const float*)d_in[10];
    const float* out_w    = (const float*)d_in[11];
    const float* out_b    = (const float*)d_in[12];
    const float* skip_w   = (const float*)d_in[13];
    const float* skip_b   = (const float*)d_in[14];
    float* out = (float*)d_out;

    float *p_xr, *p_ssm, *p_delta;
    __half *p_xch, *p_dth, *p_A2h, *p_Binh, *p_Bxph, *p_Bdth, *p_B2h;
    cudaGetSymbolAddress((void**)&p_xr,    g_xr);
    cudaGetSymbolAddress((void**)&p_ssm,   g_ssm);
    cudaGetSymbolAddress((void**)&p_delta, g_delta);
    cudaGetSymbolAddress((void**)&p_xch,   g_xch);
    cudaGetSymbolAddress((void**)&p_dth,   g_dth);
    cudaGetSymbolAddress((void**)&p_A2h,   g_A2h);
    cudaGetSymbolAddress((void**)&p_Binh,  g_Binh);
    cudaGetSymbolAddress((void**)&p_Bxph,  g_Bxph);
    cudaGetSymbolAddress((void**)&p_Bdth,  g_Bdth);
    cudaGetSymbolAddress((void**)&p_B2h,   g_B2h);

    cudaFuncSetAttribute((const void*)gemm_mma<0,128>, cudaFuncAttributeMaxDynamicSharedMemorySize, GSMEM128);
    cudaFuncSetAttribute((const void*)gemm_mma<1,64>,  cudaFuncAttributeMaxDynamicSharedMemorySize, GSMEM64);
    cudaFuncSetAttribute((const void*)gemm_mma<2,128>, cudaFuncAttributeMaxDynamicSharedMemorySize, GSMEM128);

    // 0) converts
    {
        const int total = MTOT * DM + 2 * DM * DM + SSMW * DM + DM * DTRANK + DM * DM;
        prep_all<<<(total + 255) / 256, 256>>>(x, in_w, xproj_w, dt_w, out_w, skip_w);
    }
    // 1) in_proj
    {
        dim3 g(2 * DM / 128, MTOT / 128);
        gemm_mma<0,128><<<g, 256, GSMEM128>>>(p_A2h + DM, 2 * DM, p_Binh, DM,
                                              2 * DM, DM / 64, in_b, nullptr,
                                              p_xr, 2 * DM, nullptr);
    }
    // 2) conv + silu
    conv_silu<<<(BSZ * DM * TCH) / 256, 256>>>(conv_w, conv_b);
    // 3) x_proj (BM=64 -> 64 CTAs)
    {
        dim3 g(1, MTOT / 64);
        gemm_mma<1,64><<<g, 256, GSMEM64>>>(p_xch, DM, p_Bxph, DM,
                                            SSMW, DM / 64, xproj_b, nullptr,
                                            p_ssm, SSMW, p_dth);
    }
    // 4) dt_proj
    {
        dim3 g(DM / 128, MTOT / 128);
        gemm_mma<2,128><<<g, 256, GSMEM128>>>(p_dth, DTRANK, p_Bdth, DTRANK,
                                              DM, 1, dt_b, nullptr,
                                              p_delta, DM, nullptr);
    }
    // 5) scan
    scan_passA<<<(BSZ * NCHNK * DM) / 256, 256>>>(A_log);
    scan_combine<<<(BSZ * DM) / 256, 256>>>(A_log);
    scan_passB<<<(BSZ * NCHNK * DM) / 256, 256>>>(A_log, D_param);
    // 6) fused out+skip
    {
        dim3 g(DM / 128, MTOT / 128);
        gemm_mma<0,128><<<g, 256, GSMEM128>>>(p_A2h, 2 * DM, p_B2h, 2 * DM,
                                              DM, 2 * DM / 64, out_b, skip_b,
                                              out, DM, nullptr);
    }
}

// round 6
// speedup vs baseline: 4.8258x; 1.2689x over previous
#include <cuda_runtime.h>
#include <cuda_fp16.h>
#include <math.h>
#include <stdint.h>

// ---------------- problem dims ----------------
#define BSZ    2
#define TLEN   2048
#define DM     1024
#define NST    16
#define DTRANK 64
#define SSMW   96
#define MTOT   (BSZ*TLEN)     // 4096
#define NCHNK  64
#define CLEN   (TLEN/NCHNK)   // 32
#define TCH    64
#define TLCH   (TLEN/TCH)     // 32

// ---------------- device scratch (no allocations) ----------------
__device__ float g_xr   [(size_t)MTOT * 2 * DM];
__device__ float g_xc   [(size_t)MTOT * DM];
__device__ __half g_xch [(size_t)MTOT * DM];
__device__ float g_ssm  [(size_t)MTOT * SSMW];
__device__ __half g_dth [(size_t)MTOT * DTRANK];
__device__ float g_delta[(size_t)MTOT * DM];
__device__ float g_sp   [(size_t)BSZ * NCHNK * DM];
__device__ float g_hend [(size_t)BSZ * NCHNK * NST * DM];
__device__ float g_hinit[(size_t)BSZ * NCHNK * NST * DM];
__device__ __half g_A2h [(size_t)MTOT * 2 * DM];   // [y | x]
__device__ __half g_Binh[(size_t)2 * DM * DM];
__device__ __half g_Bxph[(size_t)SSMW * DM];
__device__ __half g_Bdth[(size_t)DM * DTRANK];
__device__ __half g_B2h [(size_t)DM * 2 * DM];     // [Wout | Wskip]

// ---------------- helpers ----------------
__device__ __forceinline__ uint32_t smem_u32(const void* p) {
    uint32_t a;
    asm("{ .reg .u64 t; cvta.to.shared.u64 t, %1; cvt.u32.u64 %0, t; }" : "=r"(a) : "l"(p));
    return a;
}
#define SW128(o) ((o) ^ (((o) >> 3) & 0x70))

__device__ __forceinline__ void ldm_x4(uint32_t* r, uint32_t addr) {
    asm volatile("ldmatrix.sync.aligned.m8n8.x4.shared.b16 {%0,%1,%2,%3}, [%4];"
                 : "=r"(r[0]), "=r"(r[1]), "=r"(r[2]), "=r"(r[3]) : "r"(addr));
}
__device__ __forceinline__ void mma_f16(float* d, const uint32_t* a, const uint32_t* b) {
    asm volatile("mma.sync.aligned.m16n8k16.row.col.f32.f16.f16.f32 "
                 "{%0,%1,%2,%3}, {%4,%5,%6,%7}, {%8,%9}, {%0,%1,%2,%3};"
                 : "+f"(d[0]), "+f"(d[1]), "+f"(d[2]), "+f"(d[3])
                 : "r"(a[0]), "r"(a[1]), "r"(a[2]), "r"(a[3]), "r"(b[0]), "r"(b[1]));
}

// ---------------- HMMA fp16 GEMM, tile BM x 128, 3-stage cp.async,
//                  fragment double-buffered mainloop -------------------------
// MODE 0: C = acc + bias (+ bias2)
// MODE 1: ssm fp32 (ldc=96) + dt fp16
// MODE 2: delta = softplus(acc+bias)
template<int MODE, int BM>
__global__ void __launch_bounds__(256, 2)
gemm_mma(const __half* __restrict__ A, int lda,
         const __half* __restrict__ B, int ldb,
         int Ntot, int KT,
         const float* __restrict__ bias, const float* __restrict__ bias2,
         float* __restrict__ C, int ldc,
         __half* __restrict__ dth)
{
    constexpr int ABYTES = BM * 128;
    constexpr int STG    = ABYTES + 16384;
    constexpr int NT     = (BM == 128) ? 8 : 4;

    extern __shared__ char smem[];
    const uint32_t sb  = smem_u32(smem);
    const int tid  = threadIdx.x;
    const int wid  = tid >> 5;
    const int lane = tid & 31;
    const int bm   = blockIdx.y * BM;
    const int bn   = blockIdx.x * 128;
    const int wrow = (BM == 128) ? (wid & 3) * 32 : (wid & 1) * 32;
    const int wcol = (BM == 128) ? (wid >> 2) * 64 : (wid >> 1) * 32;

    float acc[2][NT][4];
#pragma unroll
    for (int m = 0; m < 2; m++)
#pragma unroll
        for (int n = 0; n < NT; n++)
#pragma unroll
            for (int v = 0; v < 4; v++) acc[m][n][v] = 0.f;

    auto load_stage = [&](int kt, int s) {
        uint32_t stg = sb + s * STG;
        int koff = kt * 64;
#pragma unroll
        for (int i = 0; i < BM / 32; i++) {
            int chunk = tid + i * 256;
            int row = chunk >> 3, c16 = chunk & 7;
            uint32_t dst = stg + SW128(row * 128 + c16 * 16);
            const __half* src = A + (size_t)(bm + row) * lda + koff + c16 * 8;
            asm volatile("cp.async.cg.shared.global [%0], [%1], 16;"
                         :: "r"(dst), "l"(src) : "memory");
        }
#pragma unroll
        for (int i = 0; i < 4; i++) {
            int chunk = tid + i * 256;
            int row = chunk >> 3, c16 = chunk & 7;
            uint32_t dst = stg + ABYTES + SW128(row * 128 + c16 * 16);
            int gr = bn + row;
            int sz = 16;
            if (gr >= Ntot) { gr = 0; sz = 0; }
            const __half* src = B + (size_t)gr * ldb + koff + c16 * 8;
            asm volatile("cp.async.cg.shared.global [%0], [%1], 16, %2;"
                         :: "r"(dst), "l"(src), "r"(sz) : "memory");
        }
        asm volatile("cp.async.commit_group;" ::: "memory");
    };

    const int g = lane >> 3, r = lane & 7;
    // precomputed ldmatrix base offsets (per-thread, k=0)
    const uint32_t aoff0 = (wrow + (g & 1) * 8 + r) * 128 + (g >> 1) * 16;
    const uint32_t boff0 = (wcol + (g >> 1) * 8 + r) * 128 + (g & 1) * 16;

    uint32_t afr[2][2][4];          // [buf][m16 tile][reg]
    uint32_t bfr[2][NT][2];         // [buf][n8 tile][reg]

    auto ld_frags = [&](uint32_t stg, int ks, int buf) {
        const int kByte = ks * 32;
#pragma unroll
        for (int m = 0; m < 2; m++)
            ldm_x4(afr[buf][m], stg + SW128(aoff0 + m * 16 * 128 + kByte));
#pragma unroll
        for (int nb = 0; nb < NT / 2; nb++) {
            uint32_t t[4];
            ldm_x4(t, stg + ABYTES + SW128(boff0 + nb * 16 * 128 + kByte));
            bfr[buf][nb * 2][0] = t[0]; bfr[buf][nb * 2][1] = t[1];
            bfr[buf][nb * 2 + 1][0] = t[2]; bfr[buf][nb * 2 + 1][1] = t[3];
        }
    };
    auto do_mma = [&](int buf) {
#pragma unroll
        for (int m = 0; m < 2; m++)
#pragma unroll
            for (int n = 0; n < NT; n++)
                mma_f16(acc[m][n], afr[buf][m], bfr[buf][n]);
    };

    int pf = KT < 2 ? KT : 2;
    for (int s = 0; s < pf; s++) load_stage(s, s);

    for (int kt = 0; kt < KT; kt++) {
        if (kt + 1 < KT) asm volatile("cp.async.wait_group 1;" ::: "memory");
        else             asm volatile("cp.async.wait_group 0;" ::: "memory");
        __syncthreads();
        if (kt + 2 < KT) load_stage(kt + 2, (kt + 2) % 3);

        uint32_t stg = sb + (kt % 3) * STG;
        ld_frags(stg, 0, 0);
#pragma unroll
        for (int ks = 0; ks < 4; ks++) {
            int cur = ks & 1;
            if (ks < 3) ld_frags(stg, ks + 1, cur ^ 1);
            do_mma(cur);
        }
    }
    __syncthreads();

    // epilogue staging
    float* epi = (float*)smem;
#pragma unroll
    for (int m = 0; m < 2; m++)
#pragma unroll
        for (int n = 0; n < NT; n++) {
            int row = wrow + m * 16 + (lane >> 2);
            int col = wcol + n * 8 + (lane & 3) * 2;
            epi[row * 128 + col]           = acc[m][n][0];
            epi[row * 128 + col + 1]       = acc[m][n][1];
            epi[(row + 8) * 128 + col]     = acc[m][n][2];
            epi[(row + 8) * 128 + col + 1] = acc[m][n][3];
        }
    __syncthreads();

    const float4* epi4 = (const float4*)epi;
    constexpr int EIT = BM / 8;
    if (MODE == 0) {
#pragma unroll 4
        for (int i = 0; i < EIT; i++) {
            int e = tid + i * 256;
            int row = e >> 5, c4 = e & 31;
            float4 v = epi4[e];
            int n = bn + c4 * 4;
            v.x += bias[n + 0]; v.y += bias[n + 1]; v.z += bias[n + 2]; v.w += bias[n + 3];
            if (bias2) {
                v.x += bias2[n + 0]; v.y += bias2[n + 1]; v.z += bias2[n + 2]; v.w += bias2[n + 3];
            }
            *(float4*)(C + (size_t)(bm + row) * ldc + n) = v;
        }
    } else if (MODE == 2) {
#pragma unroll 4
        for (int i = 0; i < EIT; i++) {
            int e = tid + i * 256;
            int row = e >> 5, c4 = e & 31;
            float4 v = epi4[e];
            int n = bn + c4 * 4;
            v.x += bias[n + 0]; v.y += bias[n + 1]; v.z += bias[n + 2]; v.w += bias[n + 3];
            float4 sp;
            sp.x = (v.x > 20.f) ? v.x : log1pf(expf(v.x));
            sp.y = (v.y > 20.f) ? v.y : log1pf(expf(v.y));
            sp.z = (v.z > 20.f) ? v.z : log1pf(expf(v.z));
            sp.w = (v.w > 20.f) ? v.w : log1pf(expf(v.w));
            *(float4*)(C + (size_t)(bm + row) * DM + n) = sp;
        }
    } else { // MODE 1: x_proj, Ntot = 96
        for (int i = 0; i < EIT; i++) {
            int e = tid + i * 256;
            int row = e >> 5, c4 = e & 31;
            if (c4 >= 24) continue;
            float4 v = epi4[e];
            int n = c4 * 4;
            v.x += bias[n + 0]; v.y += bias[n + 1]; v.z += bias[n + 2]; v.w += bias[n + 3];
            *(float4*)(C + (size_t)(bm + row) * SSMW + n) = v;
            if (c4 < 16) {
                size_t di = (size_t)(bm + row) * DTRANK + n;
                __half2* dst = (__half2*)(dth + di);
                dst[0] = __floats2half2_rn(v.x, v.y);
                dst[1] = __floats2half2_rn(v.z, v.w);
            }
        }
    }
}

#define GSMEM128 (3 * (128 * 128 + 16384))   // 98304
#define GSMEM64  (3 * (64 * 128 + 16384))    // 73728

// ---------------- fused converts ----------------
__global__ void prep_all(const float* __restrict__ x, const float* __restrict__ in_w,
                         const float* __restrict__ xproj_w, const float* __restrict__ dt_w,
                         const float* __restrict__ out_w, const float* __restrict__ skip_w)
{
    const int NX  = MTOT * DM;
    const int NIN = 2 * DM * DM;
    const int NXP = SSMW * DM;
    const int NDT = DM * DTRANK;
    const int NO  = DM * DM;
    int i = blockIdx.x * 256 + threadIdx.x;
    if (i < NX) {
        int m = i >> 10, c = i & 1023;
        g_A2h[(size_t)m * 2048 + 1024 + c] = __float2half(x[i]);
        return;
    }
    i -= NX;
    if (i < NIN) { g_Binh[i] = __float2half(in_w[i]); return; }
    i -= NIN;
    if (i < NXP) { g_Bxph[i] = __float2half(xproj_w[i]); return; }
    i -= NXP;
    if (i < NDT) { g_Bdth[i] = __float2half(dt_w[i]); return; }
    i -= NDT;
    if (i < NO) {
        int m = i >> 10, c = i & 1023;
        size_t o = (size_t)m * 2048;
        g_B2h[o + c]        = __float2half(out_w[i]);
        g_B2h[o + 1024 + c] = __float2half(skip_w[i]);
    }
}

// ---------------- depthwise causal conv (k=4) + silu ------------------------
__global__ void conv_silu(const float* __restrict__ cw, const float* __restrict__ cb)
{
    int gid = blockIdx.x * blockDim.x + threadIdx.x;
    if (gid >= BSZ * DM * TCH) return;
    int d  = gid % DM;
    int r  = gid / DM;
    int tc = r % TCH;
    int b  = r / TCH;

    float w0 = cw[d * 4 + 0], w1 = cw[d * 4 + 1], w2 = cw[d * 4 + 2], w3 = cw[d * 4 + 3];
    float bias = cb[d];
    int t0 = tc * TLCH;

    const float* xin = g_xr + (size_t)b * TLEN * 2 * DM + d;
    float xm3 = (t0 - 3 >= 0) ? xin[(size_t)(t0 - 3) * 2 * DM] : 0.f;
    float xm2 = (t0 - 2 >= 0) ? xin[(size_t)(t0 - 2) * 2 * DM] : 0.f;
    float xm1 = (t0 - 1 >= 0) ? xin[(size_t)(t0 - 1) * 2 * DM] : 0.f;

    for (int i = 0; i < TLCH; i++) {
        int t = t0 + i;
        float x0 = xin[(size_t)t * 2 * DM];
        float a = bias;
        a = fmaf(w0, xm3, a); a = fmaf(w1, xm2, a);
        a = fmaf(w2, xm1, a); a = fmaf(w3, x0, a);
        float s = a / (1.f + __expf(-a));
        size_t o = (size_t)(b * TLEN + t) * DM + d;
        g_xc[o]  = s;
        g_xch[o] = __float2half(s);
        xm3 = xm2; xm2 = xm1; xm1 = x0;
    }
}

// ---------------- dA powers ----------------
struct AConsts {
    float Ac[NST];
    float Ac0;
    bool  geom;
};
__device__ __forceinline__ AConsts load_aconsts(const float* A_log) {
    AConsts a;
#pragma unroll
    for (int n = 0; n < NST; n++) a.Ac[n] = -__expf(A_log[n]);
    a.Ac0 = a.Ac[0];
    a.geom = true;
#pragma unroll
    for (int n = 0; n < NST; n++)
        a.geom = a.geom && (fabsf(a.Ac[n] - (float)(n + 1) * a.Ac0) <= 1e-5f * fabsf(a.Ac[n]));
    return a;
}
__device__ __forceinline__ void da_powers(const AConsts& a, float de, float* pw) {
    if (a.geom) {
        float r = __expf(a.Ac0 * de);
        pw[0] = r;
        pw[1] = pw[0] * pw[0];  pw[2] = pw[1] * pw[0];  pw[3] = pw[1] * pw[1];
        pw[4] = pw[2] * pw[1];  pw[5] = pw[2] * pw[2];  pw[6] = pw[3] * pw[2];
        pw[7] = pw[3] * pw[3];  pw[8] = pw[4] * pw[3];  pw[9] = pw[4] * pw[4];
        pw[10] = pw[5] * pw[4]; pw[11] = pw[5] * pw[5]; pw[12] = pw[6] * pw[5];
        pw[13] = pw[6] * pw[6]; pw[14] = pw[7] * pw[6]; pw[15] = pw[7] * pw[7];
    } else {
#pragma unroll
        for (int n = 0; n < NST; n++) pw[n] = __expf(a.Ac[n] * de);
    }
}

// ---------------- chunked selective scan ----------------
__global__ void scan_passA(const float* __restrict__ A_log)
{
    int gid = blockIdx.x * blockDim.x + threadIdx.x;
    if (gid >= BSZ * NCHNK * DM) return;
    int d = gid % DM;
    int r = gid / DM;
    int c = r % NCHNK;
    int b = r / NCHNK;

    AConsts a = load_aconsts(A_log);
    float h[NST];
#pragma unroll
    for (int n = 0; n < NST; n++) h[n] = 0.f;
    float sp = 0.f;

    int m0 = b * TLEN + c * CLEN;
    for (int i = 0; i < CLEN; i++) {
        int m = m0 + i;
        float de = g_delta[(size_t)m * DM + d];
        float dx = de * g_xc[(size_t)m * DM + d];
        sp += de;
        float pw[NST];
        da_powers(a, de, pw);
        const float4* bp = (const float4*)(g_ssm + (size_t)m * SSMW + DTRANK);
#pragma unroll
        for (int q = 0; q < 4; q++) {
            float4 bv = bp[q];
            h[4*q+0] = fmaf(pw[4*q+0], h[4*q+0], dx * bv.x);
            h[4*q+1] = fmaf(pw[4*q+1], h[4*q+1], dx * bv.y);
            h[4*q+2] = fmaf(pw[4*q+2], h[4*q+2], dx * bv.z);
            h[4*q+3] = fmaf(pw[4*q+3], h[4*q+3], dx * bv.w);
        }
    }
    g_sp[(size_t)(b * NCHNK + c) * DM + d] = sp;
    size_t base = (size_t)((b * NCHNK + c) * NST) * DM + d;
#pragma unroll
    for (int n = 0; n < NST; n++) g_hend[base + (size_t)n * DM] = h[n];
}

// combine parallel over (n, b, d): one state per thread, prefetch next chunk
__global__ void scan_combine(const float* __restrict__ A_log)
{
    int gid = blockIdx.x * blockDim.x + threadIdx.x;
    if (gid >= NST * BSZ * DM) return;
    int d   = gid % DM;
    int rem = gid / DM;
    int b   = rem % BSZ;
    int n   = rem / BSZ;

    float Acn = -__expf(A_log[n]);

    float h = 0.f;
    size_t spb = (size_t)b * NCHNK * DM + d;                 // sp[b,c,d]
    size_t hb  = ((size_t)b * NCHNK * NST + n) * DM + d;     // hend[b,c,n,d]

    float spv = g_sp[spb];
    float he  = g_hend[hb];
#pragma unroll 4
    for (int c = 0; c < NCHNK; c++) {
        float sp_n = 0.f, he_n = 0.f;
        if (c + 1 < NCHNK) {
            sp_n = g_sp[spb + (size_t)(c + 1) * DM];
            he_n = g_hend[hb + (size_t)(c + 1) * NST * DM];
        }
        g_hinit[hb + (size_t)c * NST * DM] = h;
        h = fmaf(__expf(Acn * spv), h, he);
        spv = sp_n; he = he_n;
    }
}

__global__ void scan_passB(const float* __restrict__ A_log, const float* __restrict__ D_param)
{
    int gid = blockIdx.x * blockDim.x + threadIdx.x;
    if (gid >= BSZ * NCHNK * DM) return;
    int d = gid % DM;
    int r = gid / DM;
    int c = r % NCHNK;
    int b = r / NCHNK;

    AConsts a = load_aconsts(A_log);
    float h[NST];
    size_t base = (size_t)((b * NCHNK + c) * NST) * DM + d;
#pragma unroll
    for (int n = 0; n < NST; n++) h[n] = g_hinit[base + (size_t)n * DM];

    float Dp = D_param[d];
    int m0 = b * TLEN + c * CLEN;

    for (int i = 0; i < CLEN; i++) {
        int m = m0 + i;
        float de = g_delta[(size_t)m * DM + d];
        float xcv = g_xc[(size_t)m * DM + d];
        float dx = de * xcv;
        float pw[NST];
        da_powers(a, de, pw);
        const float4* bp = (const float4*)(g_ssm + (size_t)m * SSMW + DTRANK);
        const float4* cp = (const float4*)(g_ssm + (size_t)m * SSMW + DTRANK + NST);
        float y = 0.f;
#pragma unroll
        for (int q = 0; q < 4; q++) {
            float4 bv = bp[q];
            float4 cv = cp[q];
            h[4*q+0] = fmaf(pw[4*q+0], h[4*q+0], dx * bv.x); y = fmaf(h[4*q+0], cv.x, y);
            h[4*q+1] = fmaf(pw[4*q+1], h[4*q+1], dx * bv.y); y = fmaf(h[4*q+1], cv.y, y);
            h[4*q+2] = fmaf(pw[4*q+2], h[4*q+2], dx * bv.z); y = fmaf(h[4*q+2], cv.z, y);
            h[4*q+3] = fmaf(pw[4*q+3], h[4*q+3], dx * bv.w); y = fmaf(h[4*q+3], cv.w, y);
        }
        y = fmaf(xcv, Dp, y);
        float res = g_xr[(size_t)m * 2 * DM + DM + d];
        float gate = res / (1.f + __expf(-res));
        g_A2h[(size_t)m * 2 * DM + d] = __float2half(y * gate);
    }
}

// ---------------- host launcher ---------------------------------------------
extern "C" void kernel_launch(void* const* d_in, const int* in_sizes, int n_in,
                              void* d_out, int out_size)
{
    const float* x        = (const float*)d_in[0];
    const float* in_w     = (const float*)d_in[1];
    const float* in_b     = (const float*)d_in[2];
    const float* conv_w   = (const float*)d_in[3];
    const float* conv_b   = (const float*)d_in[4];
    const float* xproj_w  = (const float*)d_in[5];
    const float* xproj_b  = (const float*)d_in[6];
    const float* dt_w     = (const float*)d_in[7];
    const float* dt_b     = (const float*)d_in[8];
    const float* A_log    = (const float*)d_in[9];
    const float* D_param  = (const float*)d_in[10];
    const float* out_w    = (const float*)d_in[11];
    const float* out_b    = (const float*)d_in[12];
    const float* skip_w   = (const float*)d_in[13];
    const float* skip_b   = (const float*)d_in[14];
    float* out = (float*)d_out;

    float *p_xr, *p_ssm, *p_delta;
    __half *p_xch, *p_dth, *p_A2h, *p_Binh, *p_Bxph, *p_Bdth, *p_B2h;
    cudaGetSymbolAddress((void**)&p_xr,    g_xr);
    cudaGetSymbolAddress((void**)&p_ssm,   g_ssm);
    cudaGetSymbolAddress((void**)&p_delta, g_delta);
    cudaGetSymbolAddress((void**)&p_xch,   g_xch);
    cudaGetSymbolAddress((void**)&p_dth,   g_dth);
    cudaGetSymbolAddress((void**)&p_A2h,   g_A2h);
    cudaGetSymbolAddress((void**)&p_Binh,  g_Binh);
    cudaGetSymbolAddress((void**)&p_Bxph,  g_Bxph);
    cudaGetSymbolAddress((void**)&p_Bdth,  g_Bdth);
    cudaGetSymbolAddress((void**)&p_B2h,   g_B2h);

    cudaFuncSetAttribute((const void*)gemm_mma<0,128>, cudaFuncAttributeMaxDynamicSharedMemorySize, GSMEM128);
    cudaFuncSetAttribute((const void*)gemm_mma<1,64>,  cudaFuncAttributeMaxDynamicSharedMemorySize, GSMEM64);
    cudaFuncSetAttribute((const void*)gemm_mma<2,128>, cudaFuncAttributeMaxDynamicSharedMemorySize, GSMEM128);

    // 0) converts
    {
        const int total = MTOT * DM + 2 * DM * DM + SSMW * DM + DM * DTRANK + DM * DM;
        prep_all<<<(total + 255) / 256, 256>>>(x, in_w, xproj_w, dt_w, out_w, skip_w);
    }
    // 1) in_proj
    {
        dim3 g(2 * DM / 128, MTOT / 128);
        gemm_mma<0,128><<<g, 256, GSMEM128>>>(p_A2h + DM, 2 * DM, p_Binh, DM,
                                              2 * DM, DM / 64, in_b, nullptr,
                                              p_xr, 2 * DM, nullptr);
    }
    // 2) conv + silu
    conv_silu<<<(BSZ * DM * TCH) / 256, 256>>>(conv_w, conv_b);
    // 3) x_proj (BM=64 -> 64 CTAs)
    {
        dim3 g(1, MTOT / 64);
        gemm_mma<1,64><<<g, 256, GSMEM64>>>(p_xch, DM, p_Bxph, DM,
                                            SSMW, DM / 64, xproj_b, nullptr,
                                            p_ssm, SSMW, p_dth);
    }
    // 4) dt_proj
    {
        dim3 g(DM / 128, MTOT / 128);
        gemm_mma<2,128><<<g, 256, GSMEM128>>>(p_dth, DTRANK, p_Bdth, DTRANK,
                                              DM, 1, dt_b, nullptr,
                                              p_delta, DM, nullptr);
    }
    // 5) scan
    scan_passA<<<(BSZ * NCHNK * DM) / 256, 256>>>(A_log);
    scan_combine<<<(NST * BSZ * DM) / 256, 256>>>(A_log);
    scan_passB<<<(BSZ * NCHNK * DM) / 256, 256>>>(A_log, D_param);
    // 6) fused out+skip
    {
        dim3 g(DM / 128, MTOT / 128);
        gemm_mma<0,128><<<g, 256, GSMEM128>>>(p_A2h, 2 * DM, p_B2h, 2 * DM,
                                              DM, 2 * DM / 64, out_b, skip_b,
                                              out, DM, nullptr);
    }
}